// round 11
// baseline (speedup 1.0000x reference)
#include <cuda_runtime.h>
#include <cuda_fp16.h>
#include <math.h>
#include <stdint.h>

#define BB 32
#define LL 100
#define CC 142
#define DM 512
#define DI 1024
#define NS 16
#define DTR 32
#define NL 6
#define OD 128
#define MROWS (BB*LL)
#define CPAD 160
#define SROWH 40   // smem row stride in halves: 80B, 16B-aligned, LDSM conflict-free
#define CHK 25     // scan chunk length (4 chunks of 25)

// fp32 state / GEMM outputs
__device__ __align__(16) float g_h   [MROWS*DM];
__device__ __align__(16) float g_xsp [4*MROWS*64];
__device__ __align__(16) float g_osp [2*MROWS*DM];
__device__ __align__(16) float g_dt  [MROWS*DI];
__device__ __align__(16) float g_last[BB*DM];
__device__ __align__(16) float g_hid [BB*DM];
// fp16 GEMM operands / activations
__device__ __align__(16) __half h_inw  [NL*2*DI*DM];
__device__ __align__(16) __half h_outw [NL*DM*DI];
__device__ __align__(16) __half h_xprojw[NL*64*DI];
__device__ __align__(16) __half h_dtw  [NL*DI*DTR];
__device__ __align__(16) __half h_xpad [MROWS*CPAD];
__device__ __align__(16) __half h_wpad [DM*CPAD];
__device__ __align__(16) __half h_hn   [MROWS*DM];
__device__ __align__(16) __half h_xz   [MROWS*2*DI];
__device__ __align__(16) __half h_xc   [MROWS*DI];
__device__ __align__(16) __half h_xd   [MROWS*64];
__device__ __align__(16) __half h_yg   [MROWS*DI];

#define Q1 (NL*2*DI*DM/4)
#define Q2 (NL*DM*DI/4)
#define Q3 (NL*64*DI/4)
#define Q4 (NL*DI*DTR/4)

// one launch converts all weight tensors (vec4)
__global__ void f2h_all_kernel(const float* __restrict__ in_w, const float* __restrict__ out_w,
                               const float* __restrict__ xproj_w, const float* __restrict__ dt_w)
{
    int i = blockIdx.x * 256 + threadIdx.x;
    const float* src; __half* dst; int k;
    if (i < Q1)                { src = in_w;    dst = h_inw;    k = i; }
    else if (i < Q1+Q2)        { src = out_w;   dst = h_outw;   k = i - Q1; }
    else if (i < Q1+Q2+Q3)     { src = xproj_w; dst = h_xprojw; k = i - Q1 - Q2; }
    else if (i < Q1+Q2+Q3+Q4)  { src = dt_w;    dst = h_dtw;    k = i - Q1 - Q2 - Q3; }
    else return;
    float4 v = ((const float4*)src)[k];
    __half2* d2 = (__half2*)dst;
    d2[k*2]   = __floats2half2_rn(v.x, v.y);
    d2[k*2+1] = __floats2half2_rn(v.z, v.w);
}

// pad + convert embed operands (K=142 -> 160, zero tail)
__global__ void pad_kernel(const float* __restrict__ x, const float* __restrict__ w)
{
    int i = blockIdx.x * 256 + threadIdx.x;
    if (i < MROWS*CPAD) {
        int m = i / CPAD, c = i % CPAD;
        h_xpad[i] = (c < CC) ? __float2half(x[m*CC + c]) : __half(0.f);
    }
    int j = i - MROWS*CPAD;
    if (j >= 0 && j < DM*CPAD) {
        int m = j / CPAD, c = j % CPAD;
        h_wpad[j] = (c < CC) ? __float2half(w[m*CC + c]) : __half(0.f);
    }
}

__device__ __forceinline__ void mma_f16(float* c, const unsigned* a, const unsigned* b)
{
    asm volatile(
        "mma.sync.aligned.m16n8k16.row.col.f32.f16.f16.f32 "
        "{%0,%1,%2,%3}, {%4,%5,%6,%7}, {%8,%9}, {%0,%1,%2,%3};"
        : "+f"(c[0]), "+f"(c[1]), "+f"(c[2]), "+f"(c[3])
        : "r"(a[0]), "r"(a[1]), "r"(a[2]), "r"(a[3]),
          "r"(b[0]), "r"(b[1]));
}
#define LDSM4(r0,r1,r2,r3,addr) \
    asm volatile("ldmatrix.sync.aligned.m8n8.x4.shared.b16 {%0,%1,%2,%3}, [%4];" \
                 : "=r"(r0),"=r"(r1),"=r"(r2),"=r"(r3) : "r"(addr))
__device__ __forceinline__ void cp16(unsigned dst, const __half* src) {
    asm volatile("cp.async.cg.shared.global [%0], [%1], 16;\n" :: "r"(dst), "l"(src));
}
__device__ __forceinline__ void cp_commit() { asm volatile("cp.async.commit_group;\n"); }
template<int N>
__device__ __forceinline__ void cp_wait() { asm volatile("cp.async.wait_group %0;\n" :: "n"(N)); }

// FP16 mma GEMM, ldmatrix operand fetch, 4-stage cp.async ring.
// C[M,N] = A[M,K](h) * W[N,K](h)^T (+epilogue). CTA 128 x 32*NT, 8 warps (2x4).
// blockIdx.z = split-K slice (k-offset z*Kk halves, C offset z*cOff).
// EPI: 0 fp32 store, 1 fp32 +bias+pos, 3 softplus(+bias) fp32, 4 half store
template<int NT, int EPI>
__global__ void __launch_bounds__(256) gemm_h(
    const __half* __restrict__ A, int lda,
    const __half* __restrict__ W, int ldw,
    float* __restrict__ C, int ldc,
    int Kk, int cOff,
    const float* __restrict__ bias,
    const float* __restrict__ pos)
{
    constexpr int BN = 32*NT;
    constexpr int STAGE_H = (128 + BN) * SROWH;
    constexpr int BCH = (NT >= 2) ? NT/2 : 1;
    constexpr int NPR = NT/2;

    extern __shared__ __align__(16) __half smem[];
    const unsigned smem_u = (unsigned)__cvta_generic_to_shared(smem);

    const int tid  = threadIdx.x;
    const int lane = tid & 31;
    const int wid  = tid >> 5;
    const int warp_m = wid & 1;
    const int warp_n = wid >> 1;
    const int m0 = blockIdx.y * 128;
    const int n0 = blockIdx.x * BN;
    const int zoff = blockIdx.z * Kk;

    unsigned sA[2]; const __half* gA[2];
    #pragma unroll
    for (int j = 0; j < 2; j++) {
        int u = tid + j*256, r = u >> 2, kc = (u & 3)*8;
        sA[j] = smem_u + (r*SROWH + kc)*2;
        gA[j] = A + (size_t)(m0 + r)*lda + zoff + kc;
    }
    unsigned sB[BCH]; const __half* gB[BCH];
    #pragma unroll
    for (int j = 0; j < BCH; j++) {
        int u = tid + j*256, r = u >> 2, kc = (u & 3)*8;
        sB[j] = smem_u + ((128 + r)*SROWH + kc)*2;
        gB[j] = W + (size_t)(n0 + r)*ldw + zoff + kc;
    }

    const int sub = lane >> 3, r8 = lane & 7;
    unsigned aoff[2][4];
    #pragma unroll
    for (int ks = 0; ks < 2; ks++)
        #pragma unroll
        for (int mt = 0; mt < 4; mt++) {
            int row = warp_m*64 + mt*16 + (sub & 1)*8 + r8;
            int kb  = ks*16 + (sub >> 1)*8;
            aoff[ks][mt] = (unsigned)((row*SROWH + kb)*2);
        }
    unsigned boff[2][NPR];
    #pragma unroll
    for (int ks = 0; ks < 2; ks++)
        #pragma unroll
        for (int pr = 0; pr < NPR; pr++) {
            int nt2 = sub >> 1;
            int kb  = ks*16 + (sub & 1)*8;
            int row = 128 + warp_n*(NT*8) + (pr*2 + nt2)*8 + r8;
            boff[ks][pr] = (unsigned)((row*SROWH + kb)*2);
        }

    const int iters = Kk >> 5;

    #pragma unroll
    for (int s = 0; s < 3; s++) {
        if (s < iters) {
            int ko = s*32;
            unsigned so = (unsigned)(s*STAGE_H*2);
            #pragma unroll
            for (int j = 0; j < 2; j++)   cp16(sA[j] + so, gA[j] + ko);
            #pragma unroll
            for (int j = 0; j < BCH; j++) cp16(sB[j] + so, gB[j] + ko);
        }
        cp_commit();
    }

    float acc[4][NT][4];
    #pragma unroll
    for (int i = 0; i < 4; i++)
        #pragma unroll
        for (int j = 0; j < NT; j++)
            #pragma unroll
            for (int r = 0; r < 4; r++) acc[i][j][r] = 0.f;

    int stg = 0;
    for (int it = 0; it < iters; it++) {
        cp_wait<2>();
        __syncthreads();

        {
            int nit = it + 3;
            if (nit < iters) {
                int ko = nit*32;
                int ns = (stg + 3) & 3;
                unsigned so = (unsigned)(ns*STAGE_H*2);
                #pragma unroll
                for (int j = 0; j < 2; j++)   cp16(sA[j] + so, gA[j] + ko);
                #pragma unroll
                for (int j = 0; j < BCH; j++) cp16(sB[j] + so, gB[j] + ko);
            }
            cp_commit();
        }

        const unsigned sbase = smem_u + (unsigned)(stg*STAGE_H*2);

        #pragma unroll
        for (int ks = 0; ks < 2; ks++) {
            unsigned afr[4][4], bfr[NT][2];
            #pragma unroll
            for (int mt = 0; mt < 4; mt++)
                LDSM4(afr[mt][0], afr[mt][1], afr[mt][2], afr[mt][3], sbase + aoff[ks][mt]);
            #pragma unroll
            for (int pr = 0; pr < NPR; pr++)
                LDSM4(bfr[pr*2][0], bfr[pr*2][1], bfr[pr*2+1][0], bfr[pr*2+1][1],
                      sbase + boff[ks][pr]);
            #pragma unroll
            for (int mt = 0; mt < 4; mt++)
                #pragma unroll
                for (int nt = 0; nt < NT; nt++)
                    mma_f16(acc[mt][nt], afr[mt], bfr[nt]);
        }

        stg = (stg + 1) & 3;
    }

    float* Cz = C + (size_t)blockIdx.z * cOff;
    __half* Ch = (__half*)C;
    #pragma unroll
    for (int mt = 0; mt < 4; mt++) {
        #pragma unroll
        for (int rr = 0; rr < 2; rr++) {
            int r = m0 + warp_m*64 + mt*16 + (lane >> 2) + rr*8;
            #pragma unroll
            for (int nt = 0; nt < NT; nt++) {
                int c = n0 + warp_n*(NT*8) + nt*8 + (lane & 3)*2;
                float v0 = acc[mt][nt][rr*2 + 0];
                float v1 = acc[mt][nt][rr*2 + 1];
                size_t o = (size_t)r*ldc + c;
                if (EPI == 0) {
                    Cz[o]   = v0;
                    Cz[o+1] = v1;
                } else if (EPI == 1) {
                    const float* pr = pos + (size_t)(r % LL)*DM;
                    Cz[o]   = v0 + bias[c]   + pr[c];
                    Cz[o+1] = v1 + bias[c+1] + pr[c+1];
                } else if (EPI == 3) {
                    float u0 = v0 + bias[c];
                    float u1 = v1 + bias[c+1];
                    Cz[o]   = (u0 > 20.f) ? u0 : log1pf(__expf(u0));
                    Cz[o+1] = (u1 > 20.f) ? u1 : log1pf(__expf(u1));
                } else if (EPI == 4) {
                    *(__half2*)(Ch + o) = __floats2half2_rn(v0, v1);
                }
            }
        }
    }
}

// reduce 4 xproj split-K slices -> h_xd (half)
__global__ void reduce4_kernel()
{
    int i = blockIdx.x * 256 + threadIdx.x;
    if (i < MROWS*64) {
        const int S = MROWS*64;
        h_xd[i] = __float2half((g_xsp[i] + g_xsp[i + S]) + (g_xsp[i + 2*S] + g_xsp[i + 3*S]));
    }
}

__global__ void reduce_res_kernel()
{
    int i = blockIdx.x * 256 + threadIdx.x;
    if (i < MROWS*DM) {
        const int S = MROWS*DM;
        g_h[i] += g_osp[i] + g_osp[i + S];
    }
}

// LN: hn(half) = LN(h)  (first layer)
__global__ void ln_kernel(const float* __restrict__ g, const float* __restrict__ b)
{
    int row = blockIdx.x;
    const float* x = g_h + (size_t)row * DM;
    int tid = threadIdx.x;
    float v0 = x[tid], v1 = x[tid + 256];
    float s = v0 + v1, sq = v0*v0 + v1*v1;
    #pragma unroll
    for (int o = 16; o; o >>= 1) {
        s  += __shfl_xor_sync(0xffffffffu, s,  o);
        sq += __shfl_xor_sync(0xffffffffu, sq, o);
    }
    __shared__ float ss[8], ssq[8];
    if ((tid & 31) == 0) { ss[tid>>5] = s; ssq[tid>>5] = sq; }
    __syncthreads();
    float ts = 0.f, tsq = 0.f;
    #pragma unroll
    for (int i = 0; i < 8; i++) { ts += ss[i]; tsq += ssq[i]; }
    float mean = ts * (1.f/DM);
    float var  = tsq * (1.f/DM) - mean*mean;
    float rs = rsqrtf(var + 1e-5f);
    size_t ob = (size_t)row * DM;
    h_hn[ob + tid]       = __float2half((v0 - mean)*rs*g[tid]       + b[tid]);
    h_hn[ob + tid + 256] = __float2half((v1 - mean)*rs*g[tid + 256] + b[tid + 256]);
}

// fused: h += osp0+osp1, then hn(half) = LN(h)
__global__ void ln_res_kernel(const float* __restrict__ g, const float* __restrict__ b)
{
    int row = blockIdx.x;
    size_t ob = (size_t)row * DM;
    int tid = threadIdx.x;
    const int S = MROWS*DM;
    float v0 = g_h[ob + tid]       + g_osp[ob + tid]       + g_osp[ob + tid + S];
    float v1 = g_h[ob + tid + 256] + g_osp[ob + tid + 256] + g_osp[ob + tid + 256 + S];
    g_h[ob + tid]       = v0;
    g_h[ob + tid + 256] = v1;
    float s = v0 + v1, sq = v0*v0 + v1*v1;
    #pragma unroll
    for (int o = 16; o; o >>= 1) {
        s  += __shfl_xor_sync(0xffffffffu, s,  o);
        sq += __shfl_xor_sync(0xffffffffu, sq, o);
    }
    __shared__ float ss[8], ssq[8];
    if ((tid & 31) == 0) { ss[tid>>5] = s; ssq[tid>>5] = sq; }
    __syncthreads();
    float ts = 0.f, tsq = 0.f;
    #pragma unroll
    for (int i = 0; i < 8; i++) { ts += ss[i]; tsq += ssq[i]; }
    float mean = ts * (1.f/DM);
    float var  = tsq * (1.f/DM) - mean*mean;
    float rs = rsqrtf(var + 1e-5f);
    h_hn[ob + tid]       = __float2half((v0 - mean)*rs*g[tid]       + b[tid]);
    h_hn[ob + tid + 256] = __float2half((v1 - mean)*rs*g[tid + 256] + b[tid + 256]);
}

// final LN on last timestep -> g_last (fp32)
__global__ void ln_final_kernel(const float* __restrict__ g, const float* __restrict__ b)
{
    int row = blockIdx.x * LL + (LL-1);
    const float* x = g_h + (size_t)row * DM;
    int tid = threadIdx.x;
    float v0 = x[tid], v1 = x[tid + 256];
    float s = v0 + v1, sq = v0*v0 + v1*v1;
    #pragma unroll
    for (int o = 16; o; o >>= 1) {
        s  += __shfl_xor_sync(0xffffffffu, s,  o);
        sq += __shfl_xor_sync(0xffffffffu, sq, o);
    }
    __shared__ float ss[8], ssq[8];
    if ((tid & 31) == 0) { ss[tid>>5] = s; ssq[tid>>5] = sq; }
    __syncthreads();
    float ts = 0.f, tsq = 0.f;
    #pragma unroll
    for (int i = 0; i < 8; i++) { ts += ss[i]; tsq += ssq[i]; }
    float mean = ts * (1.f/DM);
    float var  = tsq * (1.f/DM) - mean*mean;
    float rs = rsqrtf(var + 1e-5f);
    size_t ob = (size_t)blockIdx.x * DM;
    g_last[ob + tid]       = (v0 - mean)*rs*g[tid]       + b[tid];
    g_last[ob + tid + 256] = (v1 - mean)*rs*g[tid + 256] + b[tid + 256];
}

// depthwise causal conv (K=4) + bias + silu ; reads half xz, writes half xc
__global__ void conv_kernel(const float* __restrict__ cw, const float* __restrict__ cb)
{
    int idx = blockIdx.x * 256 + threadIdx.x;
    if (idx >= MROWS*DI) return;
    int d = idx & (DI-1);
    int m = idx >> 10;
    int t = m % LL;
    float w0 = cw[d*4+0], w1 = cw[d*4+1], w2 = cw[d*4+2], w3 = cw[d*4+3];
    size_t rb = (size_t)m * (2*DI) + d;
    float acc = cb[d] + __half2float(h_xz[rb]) * w3;
    if (t >= 1) acc += __half2float(h_xz[rb - 1*2*DI]) * w2;
    if (t >= 2) acc += __half2float(h_xz[rb - 2*2*DI]) * w1;
    if (t >= 3) acc += __half2float(h_xz[rb - 3*2*DI]) * w0;
    float sig = 1.f / (1.f + __expf(-acc));
    h_xc[(size_t)m*DI + d] = __float2half(acc * sig);
}

// chunked two-pass scan: 4 time-chunks of 25, block = 256 threads = 64 d x 4 chunks.
// pass1: per-chunk (P = prod dA, q = chunk scan from 0); in-block prefix combine;
// pass2: exact recurrence from h_start, emit gated output.
__global__ void __launch_bounds__(256) scan_kernel(const float* __restrict__ A_log,
                                                   const float* __restrict__ Dp)
{
    int b   = blockIdx.y;
    int tid = threadIdx.x;
    int dl  = tid & 63;
    int c   = tid >> 6;                 // chunk 0..3 (uniform per warp pair)
    int d   = blockIdx.x * 64 + dl;

    __shared__ float sB[LL*NS], sC[LL*NS];
    __shared__ float sPQ[4][64][8];

    size_t bbase = (size_t)b * LL;
    for (int u = tid; u < LL*32; u += 256) {
        int t = u >> 5, j = u & 31;
        float v = __half2float(h_xd[(bbase + t)*64 + 32 + j]);
        if (j < NS) sB[t*NS + j] = v;
        else        sC[t*NS + (j - NS)] = v;
    }

    float Af[NS];
    #pragma unroll
    for (int n = 0; n < NS; n++)
        Af[n] = -__expf(A_log[(size_t)d*NS + n]);
    float base = Af[0];
    bool chain = true;
    #pragma unroll
    for (int n = 0; n < NS; n++) {
        float want = (float)(n+1) * base;
        chain = chain && (fabsf(Af[n] - want) <= 1e-4f*fabsf(want) + 1e-6f);
    }
    float Dpd = Dp[d];
    __syncthreads();

    const int t0 = c * CHK;

    // ---- pass 1: P, q over this chunk from zero state ----
    float P[NS], q[NS];
    #pragma unroll
    for (int n = 0; n < NS; n++) { P[n] = 1.f; q[n] = 0.f; }

    float dtv = g_dt[(bbase + t0)*DI + d];
    float xcv = __half2float(h_xc[(bbase + t0)*DI + d]);
    for (int s = 0; s < CHK; s++) {
        int t = t0 + s;
        float ndt = 0.f, nxc = 0.f;
        if (s + 1 < CHK) {
            size_t mn = (bbase + t + 1)*DI + d;
            ndt = g_dt[mn];
            nxc = __half2float(h_xc[mn]);
        }
        const float* Bp = &sB[t*NS];
        float dtx = dtv * xcv;
        if (chain) {
            float e1 = __expf(dtv * base);
            float dA = e1;
            #pragma unroll
            for (int n = 0; n < NS; n++) {
                P[n] *= dA;
                q[n] = fmaf(dA, q[n], dtx * Bp[n]);
                dA *= e1;
            }
        } else {
            #pragma unroll
            for (int n = 0; n < NS; n++) {
                float dA = __expf(dtv * Af[n]);
                P[n] *= dA;
                q[n] = fmaf(dA, q[n], dtx * Bp[n]);
            }
        }
        dtv = ndt; xcv = nxc;
    }

    // ---- combine: prefix over chunks (4 n's per round, 4 rounds) ----
    float hs[NS];
    #pragma unroll
    for (int r = 0; r < 4; r++) {
        #pragma unroll
        for (int j = 0; j < 4; j++) {
            sPQ[c][dl][j*2]   = P[r*4 + j];
            sPQ[c][dl][j*2+1] = q[r*4 + j];
        }
        __syncthreads();
        #pragma unroll
        for (int j = 0; j < 4; j++) {
            float h = 0.f;
            for (int cc = 0; cc < c; cc++)
                h = fmaf(sPQ[cc][dl][j*2], h, sPQ[cc][dl][j*2+1]);
            hs[r*4 + j] = h;      // h_start for this chunk
        }
        __syncthreads();
    }

    // ---- pass 2: exact recurrence from h_start, emit outputs ----
    dtv = g_dt[(bbase + t0)*DI + d];
    xcv = __half2float(h_xc[(bbase + t0)*DI + d]);
    float zv = __half2float(h_xz[(bbase + t0)*2*DI + DI + d]);
    for (int s = 0; s < CHK; s++) {
        int t = t0 + s;
        float ndt = 0.f, nxc = 0.f, nz = 0.f;
        if (s + 1 < CHK) {
            size_t mn = bbase + t + 1;
            ndt = g_dt[mn*DI + d];
            nxc = __half2float(h_xc[mn*DI + d]);
            nz  = __half2float(h_xz[mn*2*DI + DI + d]);
        }
        const float* Bp = &sB[t*NS];
        const float* Cp = &sC[t*NS];
        float dtx = dtv * xcv;
        float acc = 0.f;
        if (chain) {
            float e1 = __expf(dtv * base);
            float dA = e1;
            #pragma unroll
            for (int n = 0; n < NS; n++) {
                hs[n] = fmaf(dA, hs[n], dtx * Bp[n]);
                acc = fmaf(hs[n], Cp[n], acc);
                dA *= e1;
            }
        } else {
            #pragma unroll
            for (int n = 0; n < NS; n++) {
                float dA = __expf(dtv * Af[n]);
                hs[n] = fmaf(dA, hs[n], dtx * Bp[n]);
                acc = fmaf(hs[n], Cp[n], acc);
            }
        }
        float y = acc + Dpd * xcv;
        float sig = 1.f / (1.f + __expf(-zv));
        h_yg[(bbase + t)*DI + d] = __float2half(y * (zv * sig));
        dtv = ndt; xcv = nxc; zv = nz;
    }
}

__global__ void head1_kernel(const float* __restrict__ w, const float* __restrict__ bias)
{
    int b = blockIdx.x;
    int j = threadIdx.x;
    __shared__ float xr[DM];
    xr[j] = g_last[(size_t)b*DM + j];
    __syncthreads();
    const float4* wr = (const float4*)(w + (size_t)j*DM);
    float s = bias[j];
    #pragma unroll 4
    for (int k = 0; k < DM/4; k++) {
        float4 wv = wr[k];
        const float* xv = &xr[k*4];
        s = fmaf(wv.x, xv[0], s);
        s = fmaf(wv.y, xv[1], s);
        s = fmaf(wv.z, xv[2], s);
        s = fmaf(wv.w, xv[3], s);
    }
    g_hid[(size_t)b*DM + j] = 0.5f * s * (1.f + erff(s * 0.70710678118654752f));
}

__global__ void head2_kernel(const float* __restrict__ w, const float* __restrict__ bias,
                             float* __restrict__ out)
{
    int b = blockIdx.x;
    int o = threadIdx.x;
    __shared__ float xr[DM];
    for (int k = o; k < DM; k += 128) xr[k] = g_hid[(size_t)b*DM + k];
    __syncthreads();
    const float4* wr = (const float4*)(w + (size_t)o*DM);
    float s = bias[o];
    #pragma unroll 4
    for (int k = 0; k < DM/4; k++) {
        float4 wv = wr[k];
        const float* xv = &xr[k*4];
        s = fmaf(wv.x, xv[0], s);
        s = fmaf(wv.y, xv[1], s);
        s = fmaf(wv.z, xv[2], s);
        s = fmaf(wv.w, xv[3], s);
    }
    out[(size_t)b*OD + o] = s;
}

#define SMEMB(NT) (4*(128 + 32*(NT))*SROWH*2)

extern "C" void kernel_launch(void* const* d_in, const int* in_sizes, int n_in,
                              void* d_out, int out_size)
{
    const float* x      = (const float*)d_in[0];
    const float* inp_w  = (const float*)d_in[1];
    const float* inp_b  = (const float*)d_in[2];
    const float* pos    = (const float*)d_in[3];
    const float* norm_g = (const float*)d_in[4];
    const float* norm_b = (const float*)d_in[5];
    const float* in_w   = (const float*)d_in[6];
    const float* conv_w = (const float*)d_in[7];
    const float* conv_b = (const float*)d_in[8];
    const float* xproj_w= (const float*)d_in[9];
    const float* dt_w   = (const float*)d_in[10];
    const float* dt_b   = (const float*)d_in[11];
    const float* A_log  = (const float*)d_in[12];
    const float* Dp     = (const float*)d_in[13];
    const float* out_w  = (const float*)d_in[14];
    const float* lnf_g  = (const float*)d_in[15];
    const float* lnf_b  = (const float*)d_in[16];
    const float* op1_w  = (const float*)d_in[17];
    const float* op1_b  = (const float*)d_in[18];
    const float* op2_w  = (const float*)d_in[19];
    const float* op2_b  = (const float*)d_in[20];
    float* outp = (float*)d_out;

    __half *ph_inw, *ph_outw, *ph_xprojw, *ph_dtw, *ph_xpad, *ph_wpad, *ph_hn, *ph_xz, *ph_xc, *ph_xd, *ph_yg;
    cudaGetSymbolAddress((void**)&ph_inw,   h_inw);
    cudaGetSymbolAddress((void**)&ph_outw,  h_outw);
    cudaGetSymbolAddress((void**)&ph_xprojw,h_xprojw);
    cudaGetSymbolAddress((void**)&ph_dtw,   h_dtw);
    cudaGetSymbolAddress((void**)&ph_xpad,  h_xpad);
    cudaGetSymbolAddress((void**)&ph_wpad,  h_wpad);
    cudaGetSymbolAddress((void**)&ph_hn,    h_hn);
    cudaGetSymbolAddress((void**)&ph_xz,    h_xz);
    cudaGetSymbolAddress((void**)&ph_xc,    h_xc);
    cudaGetSymbolAddress((void**)&ph_xd,    h_xd);
    cudaGetSymbolAddress((void**)&ph_yg,    h_yg);
    float *p_h, *p_xsp, *p_osp, *p_dt;
    cudaGetSymbolAddress((void**)&p_h,   g_h);
    cudaGetSymbolAddress((void**)&p_xsp, g_xsp);
    cudaGetSymbolAddress((void**)&p_osp, g_osp);
    cudaGetSymbolAddress((void**)&p_dt,  g_dt);

    cudaFuncSetAttribute(gemm_h<4,0>, cudaFuncAttributeMaxDynamicSharedMemorySize, SMEMB(4));
    cudaFuncSetAttribute(gemm_h<4,1>, cudaFuncAttributeMaxDynamicSharedMemorySize, SMEMB(4));
    cudaFuncSetAttribute(gemm_h<4,3>, cudaFuncAttributeMaxDynamicSharedMemorySize, SMEMB(4));
    cudaFuncSetAttribute(gemm_h<4,4>, cudaFuncAttributeMaxDynamicSharedMemorySize, SMEMB(4));
    cudaFuncSetAttribute(gemm_h<2,0>, cudaFuncAttributeMaxDynamicSharedMemorySize, SMEMB(2));

    // 0) weight conversion (one launch) + embed pad/convert
    {
        int qtot = Q1 + Q2 + Q3 + Q4;
        f2h_all_kernel<<<(qtot + 255)/256, 256>>>(in_w, out_w, xproj_w, dt_w);
        int total = MROWS*CPAD + DM*CPAD;
        pad_kernel<<<(total + 255)/256, 256>>>(x, inp_w);
    }

    // 1) embed GEMM (+bias +pos), K=160 (zero-padded tail)
    {
        dim3 g(DM/128, MROWS/128);
        gemm_h<4,1><<<g, 256, SMEMB(4)>>>(ph_xpad, CPAD, ph_wpad, CPAD, p_h, DM, CPAD, 0, inp_b, pos);
    }

    // 2) layers
    for (int i = 0; i < NL; i++) {
        if (i == 0)
            ln_kernel<<<MROWS, 256>>>(norm_g, norm_b);
        else
            ln_res_kernel<<<MROWS, 256>>>(norm_g + i*DM, norm_b + i*DM);

        // in-proj -> half xz (EPI=4), ldc in half units
        dim3 g1(2*DI/128, MROWS/128);
        gemm_h<4,4><<<g1, 256, SMEMB(4)>>>(ph_hn, DM, ph_inw + (size_t)i*2*DI*DM, DM,
                                           (float*)ph_xz, 2*DI, DM, 0, nullptr, nullptr);

        conv_kernel<<<(MROWS*DI + 255)/256, 256>>>(conv_w + (size_t)i*DI*4, conv_b + (size_t)i*DI);

        // xproj: N=64 (NT=2), split-K x4 into g_xsp, reduced to h_xd
        dim3 g2(1, MROWS/128, 4);
        gemm_h<2,0><<<g2, 256, SMEMB(2)>>>(ph_xc, DI, ph_xprojw + (size_t)i*64*DI, DI,
                                           p_xsp, 64, DI/4, MROWS*64, nullptr, nullptr);
        reduce4_kernel<<<(MROWS*64 + 255)/256, 256>>>();

        // dt GEMM: N=1024, K=32 (only cols 0..31 of h_xd), softplus epilogue -> g_dt
        dim3 g3(DI/128, MROWS/128);
        gemm_h<4,3><<<g3, 256, SMEMB(4)>>>(ph_xd, 64, ph_dtw + (size_t)i*DI*DTR, DTR,
                                           p_dt, DI, DTR, 0, dt_b + (size_t)i*DI, nullptr);

        // chunked two-pass scan
        dim3 gs(DI/64, BB);
        scan_kernel<<<gs, 256>>>(A_log + (size_t)i*DI*NS, Dp + (size_t)i*DI);

        // out-proj: split-K x2 into g_osp; reduced by next ln_res
        dim3 g4(DM/128, MROWS/128, 2);
        gemm_h<4,0><<<g4, 256, SMEMB(4)>>>(ph_yg, DI, ph_outw + (size_t)i*DM*DI, DI,
                                           p_osp, DM, DI/2, MROWS*DM, nullptr, nullptr);
    }

    // 3) fold last out-proj, final LN (last timestep) + head
    reduce_res_kernel<<<(MROWS*DM + 255)/256, 256>>>();
    ln_final_kernel<<<BB, 256>>>(lnf_g, lnf_b);
    head1_kernel<<<BB, 512>>>(op1_w, op1_b);
    head2_kernel<<<BB, 128>>>(op2_w, op2_b, outp);
}

// round 12
// speedup vs baseline: 1.0638x; 1.0638x over previous
#include <cuda_runtime.h>
#include <cuda_fp16.h>
#include <math.h>
#include <stdint.h>

#define BB 32
#define LL 100
#define CC 142
#define DM 512
#define DI 1024
#define NS 16
#define DTR 32
#define NL 6
#define OD 128
#define MROWS (BB*LL)
#define CPAD 160
#define SROWH 40   // smem row stride in halves: 80B, 16B-aligned, LDSM conflict-free

// fp32 state / GEMM outputs
__device__ __align__(16) float g_h   [MROWS*DM];
__device__ __align__(16) float g_xsp [4*MROWS*64];
__device__ __align__(16) float g_osp [2*MROWS*DM];
__device__ __align__(16) float g_dt  [MROWS*DI];
__device__ __align__(16) float g_last[BB*DM];
__device__ __align__(16) float g_hid [BB*DM];
// fp16 GEMM operands / activations
__device__ __align__(16) __half h_inw  [NL*2*DI*DM];
__device__ __align__(16) __half h_outw [NL*DM*DI];
__device__ __align__(16) __half h_xprojw[NL*64*DI];
__device__ __align__(16) __half h_dtw  [NL*DI*DTR];
__device__ __align__(16) __half h_xpad [MROWS*CPAD];
__device__ __align__(16) __half h_wpad [DM*CPAD];
__device__ __align__(16) __half h_hn   [MROWS*DM];
__device__ __align__(16) __half h_xz   [MROWS*2*DI];
__device__ __align__(16) __half h_xc   [MROWS*DI];
__device__ __align__(16) __half h_xd   [MROWS*64];
__device__ __align__(16) __half h_yg   [MROWS*DI];

#define Q1 (NL*2*DI*DM/4)
#define Q2 (NL*DM*DI/4)
#define Q3 (NL*64*DI/4)
#define Q4 (NL*DI*DTR/4)

// one launch converts all weight tensors (vec4)
__global__ void f2h_all_kernel(const float* __restrict__ in_w, const float* __restrict__ out_w,
                               const float* __restrict__ xproj_w, const float* __restrict__ dt_w)
{
    int i = blockIdx.x * 256 + threadIdx.x;
    const float* src; __half* dst; int k;
    if (i < Q1)                { src = in_w;    dst = h_inw;    k = i; }
    else if (i < Q1+Q2)        { src = out_w;   dst = h_outw;   k = i - Q1; }
    else if (i < Q1+Q2+Q3)     { src = xproj_w; dst = h_xprojw; k = i - Q1 - Q2; }
    else if (i < Q1+Q2+Q3+Q4)  { src = dt_w;    dst = h_dtw;    k = i - Q1 - Q2 - Q3; }
    else return;
    float4 v = ((const float4*)src)[k];
    __half2* d2 = (__half2*)dst;
    d2[k*2]   = __floats2half2_rn(v.x, v.y);
    d2[k*2+1] = __floats2half2_rn(v.z, v.w);
}

// pad + convert embed operands (K=142 -> 160, zero tail)
__global__ void pad_kernel(const float* __restrict__ x, const float* __restrict__ w)
{
    int i = blockIdx.x * 256 + threadIdx.x;
    if (i < MROWS*CPAD) {
        int m = i / CPAD, c = i % CPAD;
        h_xpad[i] = (c < CC) ? __float2half(x[m*CC + c]) : __half(0.f);
    }
    int j = i - MROWS*CPAD;
    if (j >= 0 && j < DM*CPAD) {
        int m = j / CPAD, c = j % CPAD;
        h_wpad[j] = (c < CC) ? __float2half(w[m*CC + c]) : __half(0.f);
    }
}

__device__ __forceinline__ void mma_f16(float* c, const unsigned* a, const unsigned* b)
{
    asm volatile(
        "mma.sync.aligned.m16n8k16.row.col.f32.f16.f16.f32 "
        "{%0,%1,%2,%3}, {%4,%5,%6,%7}, {%8,%9}, {%0,%1,%2,%3};"
        : "+f"(c[0]), "+f"(c[1]), "+f"(c[2]), "+f"(c[3])
        : "r"(a[0]), "r"(a[1]), "r"(a[2]), "r"(a[3]),
          "r"(b[0]), "r"(b[1]));
}
#define LDSM4(r0,r1,r2,r3,addr) \
    asm volatile("ldmatrix.sync.aligned.m8n8.x4.shared.b16 {%0,%1,%2,%3}, [%4];" \
                 : "=r"(r0),"=r"(r1),"=r"(r2),"=r"(r3) : "r"(addr))
__device__ __forceinline__ void cp16(unsigned dst, const __half* src) {
    asm volatile("cp.async.cg.shared.global [%0], [%1], 16;\n" :: "r"(dst), "l"(src));
}
__device__ __forceinline__ void cp_commit() { asm volatile("cp.async.commit_group;\n"); }
template<int N>
__device__ __forceinline__ void cp_wait() { asm volatile("cp.async.wait_group %0;\n" :: "n"(N)); }

// FP16 mma GEMM, ldmatrix operand fetch, 4-stage cp.async ring.
// C[M,N] = A[M,K](h) * W[N,K](h)^T (+epilogue). CTA 128 x 32*NT, 8 warps (2x4).
// blockIdx.z = split-K slice (k-offset z*Kk halves, C offset z*cOff).
// EPI: 0 fp32 store, 1 fp32 +bias+pos, 3 softplus(+bias), 4 half store
template<int NT, int EPI>
__global__ void __launch_bounds__(256) gemm_h(
    const __half* __restrict__ A, int lda,
    const __half* __restrict__ W, int ldw,
    float* __restrict__ C, int ldc,
    int Kk, int cOff,
    const float* __restrict__ bias,
    const float* __restrict__ pos)
{
    constexpr int BN = 32*NT;
    constexpr int STAGE_H = (128 + BN) * SROWH;
    constexpr int BCH = (NT >= 2) ? NT/2 : 1;
    constexpr int NPR = NT/2;

    extern __shared__ __align__(16) __half smem[];
    const unsigned smem_u = (unsigned)__cvta_generic_to_shared(smem);

    const int tid  = threadIdx.x;
    const int lane = tid & 31;
    const int wid  = tid >> 5;
    const int warp_m = wid & 1;
    const int warp_n = wid >> 1;
    const int m0 = blockIdx.y * 128;
    const int n0 = blockIdx.x * BN;
    const int zoff = blockIdx.z * Kk;

    unsigned sA[2]; const __half* gA[2];
    #pragma unroll
    for (int j = 0; j < 2; j++) {
        int u = tid + j*256, r = u >> 2, kc = (u & 3)*8;
        sA[j] = smem_u + (r*SROWH + kc)*2;
        gA[j] = A + (size_t)(m0 + r)*lda + zoff + kc;
    }
    unsigned sB[BCH]; const __half* gB[BCH];
    #pragma unroll
    for (int j = 0; j < BCH; j++) {
        int u = tid + j*256, r = u >> 2, kc = (u & 3)*8;
        sB[j] = smem_u + ((128 + r)*SROWH + kc)*2;
        gB[j] = W + (size_t)(n0 + r)*ldw + zoff + kc;
    }

    const int sub = lane >> 3, r8 = lane & 7;
    unsigned aoff[2][4];
    #pragma unroll
    for (int ks = 0; ks < 2; ks++)
        #pragma unroll
        for (int mt = 0; mt < 4; mt++) {
            int row = warp_m*64 + mt*16 + (sub & 1)*8 + r8;
            int kb  = ks*16 + (sub >> 1)*8;
            aoff[ks][mt] = (unsigned)((row*SROWH + kb)*2);
        }
    unsigned boff[2][NPR];
    #pragma unroll
    for (int ks = 0; ks < 2; ks++)
        #pragma unroll
        for (int pr = 0; pr < NPR; pr++) {
            int nt2 = sub >> 1;
            int kb  = ks*16 + (sub & 1)*8;
            int row = 128 + warp_n*(NT*8) + (pr*2 + nt2)*8 + r8;
            boff[ks][pr] = (unsigned)((row*SROWH + kb)*2);
        }

    const int iters = Kk >> 5;

    #pragma unroll
    for (int s = 0; s < 3; s++) {
        if (s < iters) {
            int ko = s*32;
            unsigned so = (unsigned)(s*STAGE_H*2);
            #pragma unroll
            for (int j = 0; j < 2; j++)   cp16(sA[j] + so, gA[j] + ko);
            #pragma unroll
            for (int j = 0; j < BCH; j++) cp16(sB[j] + so, gB[j] + ko);
        }
        cp_commit();
    }

    float acc[4][NT][4];
    #pragma unroll
    for (int i = 0; i < 4; i++)
        #pragma unroll
        for (int j = 0; j < NT; j++)
            #pragma unroll
            for (int r = 0; r < 4; r++) acc[i][j][r] = 0.f;

    int stg = 0;
    for (int it = 0; it < iters; it++) {
        cp_wait<2>();
        __syncthreads();

        {
            int nit = it + 3;
            if (nit < iters) {
                int ko = nit*32;
                int ns = (stg + 3) & 3;
                unsigned so = (unsigned)(ns*STAGE_H*2);
                #pragma unroll
                for (int j = 0; j < 2; j++)   cp16(sA[j] + so, gA[j] + ko);
                #pragma unroll
                for (int j = 0; j < BCH; j++) cp16(sB[j] + so, gB[j] + ko);
            }
            cp_commit();
        }

        const unsigned sbase = smem_u + (unsigned)(stg*STAGE_H*2);

        #pragma unroll
        for (int ks = 0; ks < 2; ks++) {
            unsigned afr[4][4], bfr[NT][2];
            #pragma unroll
            for (int mt = 0; mt < 4; mt++)
                LDSM4(afr[mt][0], afr[mt][1], afr[mt][2], afr[mt][3], sbase + aoff[ks][mt]);
            #pragma unroll
            for (int pr = 0; pr < NPR; pr++)
                LDSM4(bfr[pr*2][0], bfr[pr*2][1], bfr[pr*2+1][0], bfr[pr*2+1][1],
                      sbase + boff[ks][pr]);
            #pragma unroll
            for (int mt = 0; mt < 4; mt++)
                #pragma unroll
                for (int nt = 0; nt < NT; nt++)
                    mma_f16(acc[mt][nt], afr[mt], bfr[nt]);
        }

        stg = (stg + 1) & 3;
    }

    float* Cz = C + (size_t)blockIdx.z * cOff;
    __half* Ch = (__half*)C;
    #pragma unroll
    for (int mt = 0; mt < 4; mt++) {
        #pragma unroll
        for (int rr = 0; rr < 2; rr++) {
            int r = m0 + warp_m*64 + mt*16 + (lane >> 2) + rr*8;
            #pragma unroll
            for (int nt = 0; nt < NT; nt++) {
                int c = n0 + warp_n*(NT*8) + nt*8 + (lane & 3)*2;
                float v0 = acc[mt][nt][rr*2 + 0];
                float v1 = acc[mt][nt][rr*2 + 1];
                size_t o = (size_t)r*ldc + c;
                if (EPI == 0) {
                    Cz[o]   = v0;
                    Cz[o+1] = v1;
                } else if (EPI == 1) {
                    const float* pr = pos + (size_t)(r % LL)*DM;
                    Cz[o]   = v0 + bias[c]   + pr[c];
                    Cz[o+1] = v1 + bias[c+1] + pr[c+1];
                } else if (EPI == 3) {
                    float u0 = v0 + bias[c];
                    float u1 = v1 + bias[c+1];
                    Cz[o]   = (u0 > 20.f) ? u0 : log1pf(__expf(u0));
                    Cz[o+1] = (u1 > 20.f) ? u1 : log1pf(__expf(u1));
                } else if (EPI == 4) {
                    *(__half2*)(Ch + o) = __floats2half2_rn(v0, v1);
                }
            }
        }
    }
}

// reduce 4 xproj split-K slices -> h_xd (half)
__global__ void reduce4_kernel()
{
    int i = blockIdx.x * 256 + threadIdx.x;
    if (i < MROWS*64) {
        const int S = MROWS*64;
        h_xd[i] = __float2half((g_xsp[i] + g_xsp[i + S]) + (g_xsp[i + 2*S] + g_xsp[i + 3*S]));
    }
}

__global__ void reduce_res_kernel()
{
    int i = blockIdx.x * 256 + threadIdx.x;
    if (i < MROWS*DM) {
        const int S = MROWS*DM;
        g_h[i] += g_osp[i] + g_osp[i + S];
    }
}

// LN: hn(half) = LN(h)  (first layer)
__global__ void ln_kernel(const float* __restrict__ g, const float* __restrict__ b)
{
    int row = blockIdx.x;
    const float* x = g_h + (size_t)row * DM;
    int tid = threadIdx.x;
    float v0 = x[tid], v1 = x[tid + 256];
    float s = v0 + v1, sq = v0*v0 + v1*v1;
    #pragma unroll
    for (int o = 16; o; o >>= 1) {
        s  += __shfl_xor_sync(0xffffffffu, s,  o);
        sq += __shfl_xor_sync(0xffffffffu, sq, o);
    }
    __shared__ float ss[8], ssq[8];
    if ((tid & 31) == 0) { ss[tid>>5] = s; ssq[tid>>5] = sq; }
    __syncthreads();
    float ts = 0.f, tsq = 0.f;
    #pragma unroll
    for (int i = 0; i < 8; i++) { ts += ss[i]; tsq += ssq[i]; }
    float mean = ts * (1.f/DM);
    float var  = tsq * (1.f/DM) - mean*mean;
    float rs = rsqrtf(var + 1e-5f);
    size_t ob = (size_t)row * DM;
    h_hn[ob + tid]       = __float2half((v0 - mean)*rs*g[tid]       + b[tid]);
    h_hn[ob + tid + 256] = __float2half((v1 - mean)*rs*g[tid + 256] + b[tid + 256]);
}

// fused: h += osp0+osp1, then hn(half) = LN(h)
__global__ void ln_res_kernel(const float* __restrict__ g, const float* __restrict__ b)
{
    int row = blockIdx.x;
    size_t ob = (size_t)row * DM;
    int tid = threadIdx.x;
    const int S = MROWS*DM;
    float v0 = g_h[ob + tid]       + g_osp[ob + tid]       + g_osp[ob + tid + S];
    float v1 = g_h[ob + tid + 256] + g_osp[ob + tid + 256] + g_osp[ob + tid + 256 + S];
    g_h[ob + tid]       = v0;
    g_h[ob + tid + 256] = v1;
    float s = v0 + v1, sq = v0*v0 + v1*v1;
    #pragma unroll
    for (int o = 16; o; o >>= 1) {
        s  += __shfl_xor_sync(0xffffffffu, s,  o);
        sq += __shfl_xor_sync(0xffffffffu, sq, o);
    }
    __shared__ float ss[8], ssq[8];
    if ((tid & 31) == 0) { ss[tid>>5] = s; ssq[tid>>5] = sq; }
    __syncthreads();
    float ts = 0.f, tsq = 0.f;
    #pragma unroll
    for (int i = 0; i < 8; i++) { ts += ss[i]; tsq += ssq[i]; }
    float mean = ts * (1.f/DM);
    float var  = tsq * (1.f/DM) - mean*mean;
    float rs = rsqrtf(var + 1e-5f);
    h_hn[ob + tid]       = __float2half((v0 - mean)*rs*g[tid]       + b[tid]);
    h_hn[ob + tid + 256] = __float2half((v1 - mean)*rs*g[tid + 256] + b[tid + 256]);
}

// final LN on last timestep -> g_last (fp32)
__global__ void ln_final_kernel(const float* __restrict__ g, const float* __restrict__ b)
{
    int row = blockIdx.x * LL + (LL-1);
    const float* x = g_h + (size_t)row * DM;
    int tid = threadIdx.x;
    float v0 = x[tid], v1 = x[tid + 256];
    float s = v0 + v1, sq = v0*v0 + v1*v1;
    #pragma unroll
    for (int o = 16; o; o >>= 1) {
        s  += __shfl_xor_sync(0xffffffffu, s,  o);
        sq += __shfl_xor_sync(0xffffffffu, sq, o);
    }
    __shared__ float ss[8], ssq[8];
    if ((tid & 31) == 0) { ss[tid>>5] = s; ssq[tid>>5] = sq; }
    __syncthreads();
    float ts = 0.f, tsq = 0.f;
    #pragma unroll
    for (int i = 0; i < 8; i++) { ts += ss[i]; tsq += ssq[i]; }
    float mean = ts * (1.f/DM);
    float var  = tsq * (1.f/DM) - mean*mean;
    float rs = rsqrtf(var + 1e-5f);
    size_t ob = (size_t)blockIdx.x * DM;
    g_last[ob + tid]       = (v0 - mean)*rs*g[tid]       + b[tid];
    g_last[ob + tid + 256] = (v1 - mean)*rs*g[tid + 256] + b[tid + 256];
}

// depthwise causal conv (K=4) + bias + silu ; reads half xz, writes half xc
__global__ void conv_kernel(const float* __restrict__ cw, const float* __restrict__ cb)
{
    int idx = blockIdx.x * 256 + threadIdx.x;
    if (idx >= MROWS*DI) return;
    int d = idx & (DI-1);
    int m = idx >> 10;
    int t = m % LL;
    float w0 = cw[d*4+0], w1 = cw[d*4+1], w2 = cw[d*4+2], w3 = cw[d*4+3];
    size_t rb = (size_t)m * (2*DI) + d;
    float acc = cb[d] + __half2float(h_xz[rb]) * w3;
    if (t >= 1) acc += __half2float(h_xz[rb - 1*2*DI]) * w2;
    if (t >= 2) acc += __half2float(h_xz[rb - 2*2*DI]) * w1;
    if (t >= 3) acc += __half2float(h_xz[rb - 3*2*DI]) * w0;
    float sig = 1.f / (1.f + __expf(-acc));
    h_xc[(size_t)m*DI + d] = __float2half(acc * sig);
}

// scan: B/C staged in smem, no barriers in t-loop, prefetch next inputs.
// exp-power chain replaced by log-depth tree; acc split into 4 partials.
__global__ void __launch_bounds__(128) scan_kernel(const float* __restrict__ A_log,
                                                   const float* __restrict__ Dp)
{
    int b = blockIdx.y;
    int tid = threadIdx.x;
    int d = blockIdx.x * 128 + tid;
    __shared__ float sB[LL*NS], sC[LL*NS];

    size_t bbase = (size_t)b * LL;
    for (int u = tid; u < LL*32; u += 128) {
        int t = u >> 5, j = u & 31;
        float v = __half2float(h_xd[(bbase + t)*64 + 32 + j]);
        if (j < NS) sB[t*NS + j] = v;
        else        sC[t*NS + (j - NS)] = v;
    }

    float hs[NS], Af[NS];
    #pragma unroll
    for (int n = 0; n < NS; n++) {
        hs[n] = 0.f;
        Af[n] = -__expf(A_log[(size_t)d*NS + n]);
    }
    float base = Af[0];
    bool chain = true;
    #pragma unroll
    for (int n = 0; n < NS; n++) {
        float want = (float)(n+1) * base;
        chain = chain && (fabsf(Af[n] - want) <= 1e-4f*fabsf(want) + 1e-6f);
    }
    float Dpd = Dp[d];
    __syncthreads();

    float xcv = __half2float(h_xc[bbase*DI + d]);
    float dtv = g_dt[bbase*DI + d];
    float zv  = __half2float(h_xz[bbase*2*DI + DI + d]);

    for (int t = 0; t < LL; t++) {
        float nxc = 0.f, ndt = 0.f, nz = 0.f;
        if (t + 1 < LL) {
            size_t mn = bbase + t + 1;
            nxc = __half2float(h_xc[mn*DI + d]);
            ndt = g_dt[mn*DI + d];
            nz  = __half2float(h_xz[mn*2*DI + DI + d]);
        }
        const float* Bp = &sB[t*NS];
        const float* Cp = &sC[t*NS];
        float dtx = dtv * xcv;
        float a0 = 0.f, a1 = 0.f, a2 = 0.f, a3 = 0.f;
        if (chain) {
            // log-depth power tree: pw[n] = e1^(n+1), depth 4, ILP-wide
            float e1 = __expf(dtv * base);
            float e2 = e1*e1, e4 = e2*e2, e8 = e4*e4;
            float p3 = e2*e1, p5 = e4*e1, p6 = e4*e2, p7 = e4*p3;
            float pw[NS] = { e1, e2, p3, e4, p5, p6, p7, e8,
                             e8*e1, e8*e2, e8*p3, e8*e4, e8*p5, e8*p6, e8*p7, e8*e8 };
            #pragma unroll
            for (int n = 0; n < NS; n++) {
                hs[n] = fmaf(pw[n], hs[n], dtx * Bp[n]);
                float v = hs[n] * Cp[n];
                if ((n & 3) == 0) a0 += v;
                else if ((n & 3) == 1) a1 += v;
                else if ((n & 3) == 2) a2 += v;
                else a3 += v;
            }
        } else {
            #pragma unroll
            for (int n = 0; n < NS; n++) {
                float dA = __expf(dtv * Af[n]);
                hs[n] = fmaf(dA, hs[n], dtx * Bp[n]);
                float v = hs[n] * Cp[n];
                if ((n & 3) == 0) a0 += v;
                else if ((n & 3) == 1) a1 += v;
                else if ((n & 3) == 2) a2 += v;
                else a3 += v;
            }
        }
        float acc = (a0 + a1) + (a2 + a3);
        float y = acc + Dpd * xcv;
        float sig = 1.f / (1.f + __expf(-zv));
        h_yg[(bbase + t)*DI + d] = __float2half(y * (zv * sig));
        xcv = nxc; dtv = ndt; zv = nz;
    }
}

__global__ void head1_kernel(const float* __restrict__ w, const float* __restrict__ bias)
{
    int b = blockIdx.x;
    int j = threadIdx.x;
    __shared__ float xr[DM];
    xr[j] = g_last[(size_t)b*DM + j];
    __syncthreads();
    const float4* wr = (const float4*)(w + (size_t)j*DM);
    float s = bias[j];
    #pragma unroll 4
    for (int k = 0; k < DM/4; k++) {
        float4 wv = wr[k];
        const float* xv = &xr[k*4];
        s = fmaf(wv.x, xv[0], s);
        s = fmaf(wv.y, xv[1], s);
        s = fmaf(wv.z, xv[2], s);
        s = fmaf(wv.w, xv[3], s);
    }
    g_hid[(size_t)b*DM + j] = 0.5f * s * (1.f + erff(s * 0.70710678118654752f));
}

__global__ void head2_kernel(const float* __restrict__ w, const float* __restrict__ bias,
                             float* __restrict__ out)
{
    int b = blockIdx.x;
    int o = threadIdx.x;
    __shared__ float xr[DM];
    for (int k = o; k < DM; k += 128) xr[k] = g_hid[(size_t)b*DM + k];
    __syncthreads();
    const float4* wr = (const float4*)(w + (size_t)o*DM);
    float s = bias[o];
    #pragma unroll 4
    for (int k = 0; k < DM/4; k++) {
        float4 wv = wr[k];
        const float* xv = &xr[k*4];
        s = fmaf(wv.x, xv[0], s);
        s = fmaf(wv.y, xv[1], s);
        s = fmaf(wv.z, xv[2], s);
        s = fmaf(wv.w, xv[3], s);
    }
    out[(size_t)b*OD + o] = s;
}

#define SMEMB(NT) (4*(128 + 32*(NT))*SROWH*2)

extern "C" void kernel_launch(void* const* d_in, const int* in_sizes, int n_in,
                              void* d_out, int out_size)
{
    const float* x      = (const float*)d_in[0];
    const float* inp_w  = (const float*)d_in[1];
    const float* inp_b  = (const float*)d_in[2];
    const float* pos    = (const float*)d_in[3];
    const float* norm_g = (const float*)d_in[4];
    const float* norm_b = (const float*)d_in[5];
    const float* in_w   = (const float*)d_in[6];
    const float* conv_w = (const float*)d_in[7];
    const float* conv_b = (const float*)d_in[8];
    const float* xproj_w= (const float*)d_in[9];
    const float* dt_w   = (const float*)d_in[10];
    const float* dt_b   = (const float*)d_in[11];
    const float* A_log  = (const float*)d_in[12];
    const float* Dp     = (const float*)d_in[13];
    const float* out_w  = (const float*)d_in[14];
    const float* lnf_g  = (const float*)d_in[15];
    const float* lnf_b  = (const float*)d_in[16];
    const float* op1_w  = (const float*)d_in[17];
    const float* op1_b  = (const float*)d_in[18];
    const float* op2_w  = (const float*)d_in[19];
    const float* op2_b  = (const float*)d_in[20];
    float* outp = (float*)d_out;

    __half *ph_inw, *ph_outw, *ph_xprojw, *ph_dtw, *ph_xpad, *ph_wpad, *ph_hn, *ph_xz, *ph_xc, *ph_xd, *ph_yg;
    cudaGetSymbolAddress((void**)&ph_inw,   h_inw);
    cudaGetSymbolAddress((void**)&ph_outw,  h_outw);
    cudaGetSymbolAddress((void**)&ph_xprojw,h_xprojw);
    cudaGetSymbolAddress((void**)&ph_dtw,   h_dtw);
    cudaGetSymbolAddress((void**)&ph_xpad,  h_xpad);
    cudaGetSymbolAddress((void**)&ph_wpad,  h_wpad);
    cudaGetSymbolAddress((void**)&ph_hn,    h_hn);
    cudaGetSymbolAddress((void**)&ph_xz,    h_xz);
    cudaGetSymbolAddress((void**)&ph_xc,    h_xc);
    cudaGetSymbolAddress((void**)&ph_xd,    h_xd);
    cudaGetSymbolAddress((void**)&ph_yg,    h_yg);
    float *p_h, *p_xsp, *p_osp, *p_dt;
    cudaGetSymbolAddress((void**)&p_h,   g_h);
    cudaGetSymbolAddress((void**)&p_xsp, g_xsp);
    cudaGetSymbolAddress((void**)&p_osp, g_osp);
    cudaGetSymbolAddress((void**)&p_dt,  g_dt);

    cudaFuncSetAttribute(gemm_h<4,0>, cudaFuncAttributeMaxDynamicSharedMemorySize, SMEMB(4));
    cudaFuncSetAttribute(gemm_h<4,1>, cudaFuncAttributeMaxDynamicSharedMemorySize, SMEMB(4));
    cudaFuncSetAttribute(gemm_h<4,3>, cudaFuncAttributeMaxDynamicSharedMemorySize, SMEMB(4));
    cudaFuncSetAttribute(gemm_h<4,4>, cudaFuncAttributeMaxDynamicSharedMemorySize, SMEMB(4));
    cudaFuncSetAttribute(gemm_h<2,0>, cudaFuncAttributeMaxDynamicSharedMemorySize, SMEMB(2));

    // 0) weight conversion (one launch) + embed pad/convert
    {
        int qtot = Q1 + Q2 + Q3 + Q4;
        f2h_all_kernel<<<(qtot + 255)/256, 256>>>(in_w, out_w, xproj_w, dt_w);
        int total = MROWS*CPAD + DM*CPAD;
        pad_kernel<<<(total + 255)/256, 256>>>(x, inp_w);
    }

    // 1) embed GEMM (+bias +pos), K=160 (zero-padded tail)
    {
        dim3 g(DM/128, MROWS/128);
        gemm_h<4,1><<<g, 256, SMEMB(4)>>>(ph_xpad, CPAD, ph_wpad, CPAD, p_h, DM, CPAD, 0, inp_b, pos);
    }

    // 2) layers
    for (int i = 0; i < NL; i++) {
        if (i == 0)
            ln_kernel<<<MROWS, 256>>>(norm_g, norm_b);
        else
            ln_res_kernel<<<MROWS, 256>>>(norm_g + i*DM, norm_b + i*DM);

        // in-proj -> half xz (EPI=4), ldc in half units
        dim3 g1(2*DI/128, MROWS/128);
        gemm_h<4,4><<<g1, 256, SMEMB(4)>>>(ph_hn, DM, ph_inw + (size_t)i*2*DI*DM, DM,
                                           (float*)ph_xz, 2*DI, DM, 0, nullptr, nullptr);

        conv_kernel<<<(MROWS*DI + 255)/256, 256>>>(conv_w + (size_t)i*DI*4, conv_b + (size_t)i*DI);

        // xproj: N=64 (NT=2), split-K x4 into g_xsp, reduced to h_xd
        dim3 g2(1, MROWS/128, 4);
        gemm_h<2,0><<<g2, 256, SMEMB(2)>>>(ph_xc, DI, ph_xprojw + (size_t)i*64*DI, DI,
                                           p_xsp, 64, DI/4, MROWS*64, nullptr, nullptr);
        reduce4_kernel<<<(MROWS*64 + 255)/256, 256>>>();

        // dt GEMM: N=1024, K=32 (cols 0..31 of h_xd), softplus epilogue -> g_dt
        dim3 g3(DI/128, MROWS/128);
        gemm_h<4,3><<<g3, 256, SMEMB(4)>>>(ph_xd, 64, ph_dtw + (size_t)i*DI*DTR, DTR,
                                           p_dt, DI, DTR, 0, dt_b + (size_t)i*DI, nullptr);

        // scan
        dim3 gs(DI/128, BB);
        scan_kernel<<<gs, 128>>>(A_log + (size_t)i*DI*NS, Dp + (size_t)i*DI);

        // out-proj: split-K x2 into g_osp; reduced by next ln_res
        dim3 g4(DM/128, MROWS/128, 2);
        gemm_h<4,0><<<g4, 256, SMEMB(4)>>>(ph_yg, DI, ph_outw + (size_t)i*DM*DI, DI,
                                           p_osp, DM, DI/2, MROWS*DM, nullptr, nullptr);
    }

    // 3) fold last out-proj, final LN (last timestep) + head
    reduce_res_kernel<<<(MROWS*DM + 255)/256, 256>>>();
    ln_final_kernel<<<BB, 256>>>(lnf_g, lnf_b);
    head1_kernel<<<BB, 512>>>(op1_w, op1_b);
    head2_kernel<<<BB, 128>>>(op2_w, op2_b, outp);
}

// round 13
// speedup vs baseline: 1.0848x; 1.0198x over previous
#include <cuda_runtime.h>
#include <cuda_fp16.h>
#include <math.h>
#include <stdint.h>

#define BB 32
#define LL 100
#define CC 142
#define DM 512
#define DI 1024
#define NS 16
#define DTR 32
#define NL 6
#define OD 128
#define MROWS (BB*LL)
#define CPAD 160
#define SROWH 40   // smem row stride in halves: 80B, 16B-aligned, LDSM conflict-free

// fp32 state / GEMM outputs
__device__ __align__(16) float g_h   [MROWS*DM];
__device__ __align__(16) float g_xsp [4*MROWS*64];
__device__ __align__(16) float g_last[BB*DM];
__device__ __align__(16) float g_hid [BB*DM];
// fp16 GEMM operands / activations
__device__ __align__(16) __half h_osp  [2*MROWS*DM];
__device__ __align__(16) __half h_dt   [MROWS*DI];
__device__ __align__(16) __half h_inw  [NL*2*DI*DM];
__device__ __align__(16) __half h_outw [NL*DM*DI];
__device__ __align__(16) __half h_xprojw[NL*64*DI];
__device__ __align__(16) __half h_dtw  [NL*DI*DTR];
__device__ __align__(16) __half h_xpad [MROWS*CPAD];
__device__ __align__(16) __half h_wpad [DM*CPAD];
__device__ __align__(16) __half h_hn   [MROWS*DM];
__device__ __align__(16) __half h_xz   [MROWS*2*DI];
__device__ __align__(16) __half h_xc   [MROWS*DI];
__device__ __align__(16) __half h_xd   [MROWS*64];
__device__ __align__(16) __half h_yg   [MROWS*DI];

#define Q1 (NL*2*DI*DM/4)
#define Q2 (NL*DM*DI/4)
#define Q3 (NL*64*DI/4)
#define Q4 (NL*DI*DTR/4)

// one launch converts all weight tensors (vec4)
__global__ void f2h_all_kernel(const float* __restrict__ in_w, const float* __restrict__ out_w,
                               const float* __restrict__ xproj_w, const float* __restrict__ dt_w)
{
    int i = blockIdx.x * 256 + threadIdx.x;
    const float* src; __half* dst; int k;
    if (i < Q1)                { src = in_w;    dst = h_inw;    k = i; }
    else if (i < Q1+Q2)        { src = out_w;   dst = h_outw;   k = i - Q1; }
    else if (i < Q1+Q2+Q3)     { src = xproj_w; dst = h_xprojw; k = i - Q1 - Q2; }
    else if (i < Q1+Q2+Q3+Q4)  { src = dt_w;    dst = h_dtw;    k = i - Q1 - Q2 - Q3; }
    else return;
    float4 v = ((const float4*)src)[k];
    __half2* d2 = (__half2*)dst;
    d2[k*2]   = __floats2half2_rn(v.x, v.y);
    d2[k*2+1] = __floats2half2_rn(v.z, v.w);
}

// pad + convert embed operands (K=142 -> 160, zero tail)
__global__ void pad_kernel(const float* __restrict__ x, const float* __restrict__ w)
{
    int i = blockIdx.x * 256 + threadIdx.x;
    if (i < MROWS*CPAD) {
        int m = i / CPAD, c = i % CPAD;
        h_xpad[i] = (c < CC) ? __float2half(x[m*CC + c]) : __half(0.f);
    }
    int j = i - MROWS*CPAD;
    if (j >= 0 && j < DM*CPAD) {
        int m = j / CPAD, c = j % CPAD;
        h_wpad[j] = (c < CC) ? __float2half(w[m*CC + c]) : __half(0.f);
    }
}

__device__ __forceinline__ void mma_f16(float* c, const unsigned* a, const unsigned* b)
{
    asm volatile(
        "mma.sync.aligned.m16n8k16.row.col.f32.f16.f16.f32 "
        "{%0,%1,%2,%3}, {%4,%5,%6,%7}, {%8,%9}, {%0,%1,%2,%3};"
        : "+f"(c[0]), "+f"(c[1]), "+f"(c[2]), "+f"(c[3])
        : "r"(a[0]), "r"(a[1]), "r"(a[2]), "r"(a[3]),
          "r"(b[0]), "r"(b[1]));
}
#define LDSM4(r0,r1,r2,r3,addr) \
    asm volatile("ldmatrix.sync.aligned.m8n8.x4.shared.b16 {%0,%1,%2,%3}, [%4];" \
                 : "=r"(r0),"=r"(r1),"=r"(r2),"=r"(r3) : "r"(addr))
__device__ __forceinline__ void cp16(unsigned dst, const __half* src) {
    asm volatile("cp.async.cg.shared.global [%0], [%1], 16;\n" :: "r"(dst), "l"(src));
}
__device__ __forceinline__ void cp_commit() { asm volatile("cp.async.commit_group;\n"); }
template<int N>
__device__ __forceinline__ void cp_wait() { asm volatile("cp.async.wait_group %0;\n" :: "n"(N)); }

// FP16 mma GEMM, ldmatrix operand fetch, 4-stage cp.async ring.
// C[M,N] = A[M,K](h) * W[N,K](h)^T (+epilogue). CTA 128 x 32*NT, 8 warps (2x4).
// blockIdx.z = split-K slice (k-offset z*Kk halves, C offset z*cOff).
// EPI: 0 fp32 store, 1 fp32 +bias+pos, 4 half store,
//      5 half store with split-K offset, 6 half softplus(+bias)
template<int NT, int EPI>
__global__ void __launch_bounds__(256) gemm_h(
    const __half* __restrict__ A, int lda,
    const __half* __restrict__ W, int ldw,
    float* __restrict__ C, int ldc,
    int Kk, int cOff,
    const float* __restrict__ bias,
    const float* __restrict__ pos)
{
    constexpr int BN = 32*NT;
    constexpr int STAGE_H = (128 + BN) * SROWH;
    constexpr int BCH = (NT >= 2) ? NT/2 : 1;
    constexpr int NPR = NT/2;

    extern __shared__ __align__(16) __half smem[];
    const unsigned smem_u = (unsigned)__cvta_generic_to_shared(smem);

    const int tid  = threadIdx.x;
    const int lane = tid & 31;
    const int wid  = tid >> 5;
    const int warp_m = wid & 1;
    const int warp_n = wid >> 1;
    const int m0 = blockIdx.y * 128;
    const int n0 = blockIdx.x * BN;
    const int zoff = blockIdx.z * Kk;

    unsigned sA[2]; const __half* gA[2];
    #pragma unroll
    for (int j = 0; j < 2; j++) {
        int u = tid + j*256, r = u >> 2, kc = (u & 3)*8;
        sA[j] = smem_u + (r*SROWH + kc)*2;
        gA[j] = A + (size_t)(m0 + r)*lda + zoff + kc;
    }
    unsigned sB[BCH]; const __half* gB[BCH];
    #pragma unroll
    for (int j = 0; j < BCH; j++) {
        int u = tid + j*256, r = u >> 2, kc = (u & 3)*8;
        sB[j] = smem_u + ((128 + r)*SROWH + kc)*2;
        gB[j] = W + (size_t)(n0 + r)*ldw + zoff + kc;
    }

    const int sub = lane >> 3, r8 = lane & 7;
    unsigned aoff[2][4];
    #pragma unroll
    for (int ks = 0; ks < 2; ks++)
        #pragma unroll
        for (int mt = 0; mt < 4; mt++) {
            int row = warp_m*64 + mt*16 + (sub & 1)*8 + r8;
            int kb  = ks*16 + (sub >> 1)*8;
            aoff[ks][mt] = (unsigned)((row*SROWH + kb)*2);
        }
    unsigned boff[2][NPR];
    #pragma unroll
    for (int ks = 0; ks < 2; ks++)
        #pragma unroll
        for (int pr = 0; pr < NPR; pr++) {
            int nt2 = sub >> 1;
            int kb  = ks*16 + (sub & 1)*8;
            int row = 128 + warp_n*(NT*8) + (pr*2 + nt2)*8 + r8;
            boff[ks][pr] = (unsigned)((row*SROWH + kb)*2);
        }

    const int iters = Kk >> 5;

    #pragma unroll
    for (int s = 0; s < 3; s++) {
        if (s < iters) {
            int ko = s*32;
            unsigned so = (unsigned)(s*STAGE_H*2);
            #pragma unroll
            for (int j = 0; j < 2; j++)   cp16(sA[j] + so, gA[j] + ko);
            #pragma unroll
            for (int j = 0; j < BCH; j++) cp16(sB[j] + so, gB[j] + ko);
        }
        cp_commit();
    }

    float acc[4][NT][4];
    #pragma unroll
    for (int i = 0; i < 4; i++)
        #pragma unroll
        for (int j = 0; j < NT; j++)
            #pragma unroll
            for (int r = 0; r < 4; r++) acc[i][j][r] = 0.f;

    int stg = 0;
    for (int it = 0; it < iters; it++) {
        cp_wait<2>();
        __syncthreads();

        {
            int nit = it + 3;
            if (nit < iters) {
                int ko = nit*32;
                int ns = (stg + 3) & 3;
                unsigned so = (unsigned)(ns*STAGE_H*2);
                #pragma unroll
                for (int j = 0; j < 2; j++)   cp16(sA[j] + so, gA[j] + ko);
                #pragma unroll
                for (int j = 0; j < BCH; j++) cp16(sB[j] + so, gB[j] + ko);
            }
            cp_commit();
        }

        const unsigned sbase = smem_u + (unsigned)(stg*STAGE_H*2);

        #pragma unroll
        for (int ks = 0; ks < 2; ks++) {
            unsigned afr[4][4], bfr[NT][2];
            #pragma unroll
            for (int mt = 0; mt < 4; mt++)
                LDSM4(afr[mt][0], afr[mt][1], afr[mt][2], afr[mt][3], sbase + aoff[ks][mt]);
            #pragma unroll
            for (int pr = 0; pr < NPR; pr++)
                LDSM4(bfr[pr*2][0], bfr[pr*2][1], bfr[pr*2+1][0], bfr[pr*2+1][1],
                      sbase + boff[ks][pr]);
            #pragma unroll
            for (int mt = 0; mt < 4; mt++)
                #pragma unroll
                for (int nt = 0; nt < NT; nt++)
                    mma_f16(acc[mt][nt], afr[mt], bfr[nt]);
        }

        stg = (stg + 1) & 3;
    }

    float* Cz = C + (size_t)blockIdx.z * cOff;
    __half* Ch = (__half*)C;
    __half* Chz = (__half*)C + (size_t)blockIdx.z * cOff;
    #pragma unroll
    for (int mt = 0; mt < 4; mt++) {
        #pragma unroll
        for (int rr = 0; rr < 2; rr++) {
            int r = m0 + warp_m*64 + mt*16 + (lane >> 2) + rr*8;
            #pragma unroll
            for (int nt = 0; nt < NT; nt++) {
                int c = n0 + warp_n*(NT*8) + nt*8 + (lane & 3)*2;
                float v0 = acc[mt][nt][rr*2 + 0];
                float v1 = acc[mt][nt][rr*2 + 1];
                size_t o = (size_t)r*ldc + c;
                if (EPI == 0) {
                    Cz[o]   = v0;
                    Cz[o+1] = v1;
                } else if (EPI == 1) {
                    const float* pr = pos + (size_t)(r % LL)*DM;
                    Cz[o]   = v0 + bias[c]   + pr[c];
                    Cz[o+1] = v1 + bias[c+1] + pr[c+1];
                } else if (EPI == 4) {
                    *(__half2*)(Ch + o) = __floats2half2_rn(v0, v1);
                } else if (EPI == 5) {
                    *(__half2*)(Chz + o) = __floats2half2_rn(v0, v1);
                } else if (EPI == 6) {
                    float u0 = v0 + bias[c];
                    float u1 = v1 + bias[c+1];
                    u0 = (u0 > 20.f) ? u0 : log1pf(__expf(u0));
                    u1 = (u1 > 20.f) ? u1 : log1pf(__expf(u1));
                    *(__half2*)(Ch + o) = __floats2half2_rn(u0, u1);
                }
            }
        }
    }
}

// reduce 4 xproj split-K slices -> h_xd (half)
__global__ void reduce4_kernel()
{
    int i = blockIdx.x * 256 + threadIdx.x;
    if (i < MROWS*64) {
        const int S = MROWS*64;
        h_xd[i] = __float2half((g_xsp[i] + g_xsp[i + S]) + (g_xsp[i + 2*S] + g_xsp[i + 3*S]));
    }
}

// fold the two half out-proj slices into g_h (final layer only)
__global__ void reduce_res_kernel()
{
    int i = blockIdx.x * 256 + threadIdx.x;
    if (i < MROWS*DM) {
        const int S = MROWS*DM;
        g_h[i] += __half2float(h_osp[i]) + __half2float(h_osp[i + S]);
    }
}

// LN: hn(half) = LN(h)  (first layer) ; vectorized float2/half2
__global__ void ln_kernel(const float* __restrict__ g, const float* __restrict__ b)
{
    int row = blockIdx.x;
    int tid = threadIdx.x;      // 256 threads, 2 elems each via float2
    size_t ob = (size_t)row * DM;
    float2 v = *(const float2*)&g_h[ob + tid*2];
    float s = v.x + v.y, sq = v.x*v.x + v.y*v.y;
    #pragma unroll
    for (int o = 16; o; o >>= 1) {
        s  += __shfl_xor_sync(0xffffffffu, s,  o);
        sq += __shfl_xor_sync(0xffffffffu, sq, o);
    }
    __shared__ float ss[8], ssq[8];
    if ((tid & 31) == 0) { ss[tid>>5] = s; ssq[tid>>5] = sq; }
    __syncthreads();
    float ts = 0.f, tsq = 0.f;
    #pragma unroll
    for (int i = 0; i < 8; i++) { ts += ss[i]; tsq += ssq[i]; }
    float mean = ts * (1.f/DM);
    float var  = tsq * (1.f/DM) - mean*mean;
    float rs = rsqrtf(var + 1e-5f);
    float2 gg = *(const float2*)&g[tid*2];
    float2 bb = *(const float2*)&b[tid*2];
    *(__half2*)&h_hn[ob + tid*2] =
        __floats2half2_rn((v.x - mean)*rs*gg.x + bb.x, (v.y - mean)*rs*gg.y + bb.y);
}

// fused: h += osp0+osp1 (half slices), then hn(half) = LN(h) ; vectorized
__global__ void ln_res_kernel(const float* __restrict__ g, const float* __restrict__ b)
{
    int row = blockIdx.x;
    size_t ob = (size_t)row * DM;
    int tid = threadIdx.x;
    const int S = MROWS*DM;
    float2 v = *(const float2*)&g_h[ob + tid*2];
    float2 o0 = __half22float2(*(const __half2*)&h_osp[ob + tid*2]);
    float2 o1 = __half22float2(*(const __half2*)&h_osp[ob + tid*2 + S]);
    v.x += o0.x + o1.x;
    v.y += o0.y + o1.y;
    *(float2*)&g_h[ob + tid*2] = v;
    float s = v.x + v.y, sq = v.x*v.x + v.y*v.y;
    #pragma unroll
    for (int o = 16; o; o >>= 1) {
        s  += __shfl_xor_sync(0xffffffffu, s,  o);
        sq += __shfl_xor_sync(0xffffffffu, sq, o);
    }
    __shared__ float ss[8], ssq[8];
    if ((tid & 31) == 0) { ss[tid>>5] = s; ssq[tid>>5] = sq; }
    __syncthreads();
    float ts = 0.f, tsq = 0.f;
    #pragma unroll
    for (int i = 0; i < 8; i++) { ts += ss[i]; tsq += ssq[i]; }
    float mean = ts * (1.f/DM);
    float var  = tsq * (1.f/DM) - mean*mean;
    float rs = rsqrtf(var + 1e-5f);
    float2 gg = *(const float2*)&g[tid*2];
    float2 bb = *(const float2*)&b[tid*2];
    *(__half2*)&h_hn[ob + tid*2] =
        __floats2half2_rn((v.x - mean)*rs*gg.x + bb.x, (v.y - mean)*rs*gg.y + bb.y);
}

// final LN on last timestep -> g_last (fp32)
__global__ void ln_final_kernel(const float* __restrict__ g, const float* __restrict__ b)
{
    int row = blockIdx.x * LL + (LL-1);
    const float* x = g_h + (size_t)row * DM;
    int tid = threadIdx.x;
    float v0 = x[tid], v1 = x[tid + 256];
    float s = v0 + v1, sq = v0*v0 + v1*v1;
    #pragma unroll
    for (int o = 16; o; o >>= 1) {
        s  += __shfl_xor_sync(0xffffffffu, s,  o);
        sq += __shfl_xor_sync(0xffffffffu, sq, o);
    }
    __shared__ float ss[8], ssq[8];
    if ((tid & 31) == 0) { ss[tid>>5] = s; ssq[tid>>5] = sq; }
    __syncthreads();
    float ts = 0.f, tsq = 0.f;
    #pragma unroll
    for (int i = 0; i < 8; i++) { ts += ss[i]; tsq += ssq[i]; }
    float mean = ts * (1.f/DM);
    float var  = tsq * (1.f/DM) - mean*mean;
    float rs = rsqrtf(var + 1e-5f);
    size_t ob = (size_t)blockIdx.x * DM;
    g_last[ob + tid]       = (v0 - mean)*rs*g[tid]       + b[tid];
    g_last[ob + tid + 256] = (v1 - mean)*rs*g[tid + 256] + b[tid + 256];
}

// depthwise causal conv (K=4) + bias + silu ; half2: 2 channels per thread
__global__ void conv_kernel(const float* __restrict__ cw, const float* __restrict__ cb)
{
    int idx = blockIdx.x * 256 + threadIdx.x;
    if (idx >= MROWS*DI/2) return;
    int dp = idx & (DI/2 - 1);       // channel pair
    int m  = idx / (DI/2);
    int d  = dp*2;
    int t  = m % LL;
    float4 wA = *(const float4*)&cw[d*4];       // channel d taps
    float4 wB = *(const float4*)&cw[d*4 + 4];   // channel d+1 taps
    float2 cbv = *(const float2*)&cb[d];
    size_t rb = (size_t)m * (2*DI) + d;
    float2 x0 = __half22float2(*(const __half2*)&h_xz[rb]);
    float a0 = cbv.x + x0.x * wA.w;
    float a1 = cbv.y + x0.y * wB.w;
    if (t >= 1) {
        float2 xm = __half22float2(*(const __half2*)&h_xz[rb - 1*2*DI]);
        a0 += xm.x * wA.z; a1 += xm.y * wB.z;
    }
    if (t >= 2) {
        float2 xm = __half22float2(*(const __half2*)&h_xz[rb - 2*2*DI]);
        a0 += xm.x * wA.y; a1 += xm.y * wB.y;
    }
    if (t >= 3) {
        float2 xm = __half22float2(*(const __half2*)&h_xz[rb - 3*2*DI]);
        a0 += xm.x * wA.x; a1 += xm.y * wB.x;
    }
    float s0 = a0 / (1.f + __expf(-a0));
    float s1 = a1 / (1.f + __expf(-a1));
    *(__half2*)&h_xc[(size_t)m*DI + d] = __floats2half2_rn(s0, s1);
}

// scan: B/C staged in smem, no barriers in t-loop, prefetch next inputs.
// exp-power chain via log-depth tree; acc split into 4 partials.
__global__ void __launch_bounds__(128) scan_kernel(const float* __restrict__ A_log,
                                                   const float* __restrict__ Dp)
{
    int b = blockIdx.y;
    int tid = threadIdx.x;
    int d = blockIdx.x * 128 + tid;
    __shared__ float sB[LL*NS], sC[LL*NS];

    size_t bbase = (size_t)b * LL;
    for (int u = tid; u < LL*32; u += 128) {
        int t = u >> 5, j = u & 31;
        float v = __half2float(h_xd[(bbase + t)*64 + 32 + j]);
        if (j < NS) sB[t*NS + j] = v;
        else        sC[t*NS + (j - NS)] = v;
    }

    float hs[NS], Af[NS];
    #pragma unroll
    for (int n = 0; n < NS; n++) {
        hs[n] = 0.f;
        Af[n] = -__expf(A_log[(size_t)d*NS + n]);
    }
    float base = Af[0];
    bool chain = true;
    #pragma unroll
    for (int n = 0; n < NS; n++) {
        float want = (float)(n+1) * base;
        chain = chain && (fabsf(Af[n] - want) <= 1e-4f*fabsf(want) + 1e-6f);
    }
    float Dpd = Dp[d];
    __syncthreads();

    float xcv = __half2float(h_xc[bbase*DI + d]);
    float dtv = __half2float(h_dt[bbase*DI + d]);
    float zv  = __half2float(h_xz[bbase*2*DI + DI + d]);

    for (int t = 0; t < LL; t++) {
        float nxc = 0.f, ndt = 0.f, nz = 0.f;
        if (t + 1 < LL) {
            size_t mn = bbase + t + 1;
            nxc = __half2float(h_xc[mn*DI + d]);
            ndt = __half2float(h_dt[mn*DI + d]);
            nz  = __half2float(h_xz[mn*2*DI + DI + d]);
        }
        const float* Bp = &sB[t*NS];
        const float* Cp = &sC[t*NS];
        float dtx = dtv * xcv;
        float a0 = 0.f, a1 = 0.f, a2 = 0.f, a3 = 0.f;
        if (chain) {
            float e1 = __expf(dtv * base);
            float e2 = e1*e1, e4 = e2*e2, e8 = e4*e4;
            float p3 = e2*e1, p5 = e4*e1, p6 = e4*e2, p7 = e4*p3;
            float pw[NS] = { e1, e2, p3, e4, p5, p6, p7, e8,
                             e8*e1, e8*e2, e8*p3, e8*e4, e8*p5, e8*p6, e8*p7, e8*e8 };
            #pragma unroll
            for (int n = 0; n < NS; n++) {
                hs[n] = fmaf(pw[n], hs[n], dtx * Bp[n]);
                float v = hs[n] * Cp[n];
                if ((n & 3) == 0) a0 += v;
                else if ((n & 3) == 1) a1 += v;
                else if ((n & 3) == 2) a2 += v;
                else a3 += v;
            }
        } else {
            #pragma unroll
            for (int n = 0; n < NS; n++) {
                float dA = __expf(dtv * Af[n]);
                hs[n] = fmaf(dA, hs[n], dtx * Bp[n]);
                float v = hs[n] * Cp[n];
                if ((n & 3) == 0) a0 += v;
                else if ((n & 3) == 1) a1 += v;
                else if ((n & 3) == 2) a2 += v;
                else a3 += v;
            }
        }
        float acc = (a0 + a1) + (a2 + a3);
        float y = acc + Dpd * xcv;
        float sig = 1.f / (1.f + __expf(-zv));
        h_yg[(bbase + t)*DI + d] = __float2half(y * (zv * sig));
        xcv = nxc; dtv = ndt; zv = nz;
    }
}

__global__ void head1_kernel(const float* __restrict__ w, const float* __restrict__ bias)
{
    int b = blockIdx.x;
    int j = threadIdx.x;
    __shared__ float xr[DM];
    xr[j] = g_last[(size_t)b*DM + j];
    __syncthreads();
    const float4* wr = (const float4*)(w + (size_t)j*DM);
    float s = bias[j];
    #pragma unroll 4
    for (int k = 0; k < DM/4; k++) {
        float4 wv = wr[k];
        const float* xv = &xr[k*4];
        s = fmaf(wv.x, xv[0], s);
        s = fmaf(wv.y, xv[1], s);
        s = fmaf(wv.z, xv[2], s);
        s = fmaf(wv.w, xv[3], s);
    }
    g_hid[(size_t)b*DM + j] = 0.5f * s * (1.f + erff(s * 0.70710678118654752f));
}

__global__ void head2_kernel(const float* __restrict__ w, const float* __restrict__ bias,
                             float* __restrict__ out)
{
    int b = blockIdx.x;
    int o = threadIdx.x;
    __shared__ float xr[DM];
    for (int k = o; k < DM; k += 128) xr[k] = g_hid[(size_t)b*DM + k];
    __syncthreads();
    const float4* wr = (const float4*)(w + (size_t)o*DM);
    float s = bias[o];
    #pragma unroll 4
    for (int k = 0; k < DM/4; k++) {
        float4 wv = wr[k];
        const float* xv = &xr[k*4];
        s = fmaf(wv.x, xv[0], s);
        s = fmaf(wv.y, xv[1], s);
        s = fmaf(wv.z, xv[2], s);
        s = fmaf(wv.w, xv[3], s);
    }
    out[(size_t)b*OD + o] = s;
}

#define SMEMB(NT) (4*(128 + 32*(NT))*SROWH*2)

extern "C" void kernel_launch(void* const* d_in, const int* in_sizes, int n_in,
                              void* d_out, int out_size)
{
    const float* x      = (const float*)d_in[0];
    const float* inp_w  = (const float*)d_in[1];
    const float* inp_b  = (const float*)d_in[2];
    const float* pos    = (const float*)d_in[3];
    const float* norm_g = (const float*)d_in[4];
    const float* norm_b = (const float*)d_in[5];
    const float* in_w   = (const float*)d_in[6];
    const float* conv_w = (const float*)d_in[7];
    const float* conv_b = (const float*)d_in[8];
    const float* xproj_w= (const float*)d_in[9];
    const float* dt_w   = (const float*)d_in[10];
    const float* dt_b   = (const float*)d_in[11];
    const float* A_log  = (const float*)d_in[12];
    const float* Dp     = (const float*)d_in[13];
    const float* out_w  = (const float*)d_in[14];
    const float* lnf_g  = (const float*)d_in[15];
    const float* lnf_b  = (const float*)d_in[16];
    const float* op1_w  = (const float*)d_in[17];
    const float* op1_b  = (const float*)d_in[18];
    const float* op2_w  = (const float*)d_in[19];
    const float* op2_b  = (const float*)d_in[20];
    float* outp = (float*)d_out;

    __half *ph_inw, *ph_outw, *ph_xprojw, *ph_dtw, *ph_xpad, *ph_wpad, *ph_hn, *ph_xz, *ph_xc, *ph_xd, *ph_yg, *ph_osp, *ph_dt;
    cudaGetSymbolAddress((void**)&ph_inw,   h_inw);
    cudaGetSymbolAddress((void**)&ph_outw,  h_outw);
    cudaGetSymbolAddress((void**)&ph_xprojw,h_xprojw);
    cudaGetSymbolAddress((void**)&ph_dtw,   h_dtw);
    cudaGetSymbolAddress((void**)&ph_xpad,  h_xpad);
    cudaGetSymbolAddress((void**)&ph_wpad,  h_wpad);
    cudaGetSymbolAddress((void**)&ph_hn,    h_hn);
    cudaGetSymbolAddress((void**)&ph_xz,    h_xz);
    cudaGetSymbolAddress((void**)&ph_xc,    h_xc);
    cudaGetSymbolAddress((void**)&ph_xd,    h_xd);
    cudaGetSymbolAddress((void**)&ph_yg,    h_yg);
    cudaGetSymbolAddress((void**)&ph_osp,   h_osp);
    cudaGetSymbolAddress((void**)&ph_dt,    h_dt);
    float *p_h, *p_xsp;
    cudaGetSymbolAddress((void**)&p_h,   g_h);
    cudaGetSymbolAddress((void**)&p_xsp, g_xsp);

    cudaFuncSetAttribute(gemm_h<4,1>, cudaFuncAttributeMaxDynamicSharedMemorySize, SMEMB(4));
    cudaFuncSetAttribute(gemm_h<4,4>, cudaFuncAttributeMaxDynamicSharedMemorySize, SMEMB(4));
    cudaFuncSetAttribute(gemm_h<4,5>, cudaFuncAttributeMaxDynamicSharedMemorySize, SMEMB(4));
    cudaFuncSetAttribute(gemm_h<4,6>, cudaFuncAttributeMaxDynamicSharedMemorySize, SMEMB(4));
    cudaFuncSetAttribute(gemm_h<2,0>, cudaFuncAttributeMaxDynamicSharedMemorySize, SMEMB(2));

    // 0) weight conversion (one launch) + embed pad/convert
    {
        int qtot = Q1 + Q2 + Q3 + Q4;
        f2h_all_kernel<<<(qtot + 255)/256, 256>>>(in_w, out_w, xproj_w, dt_w);
        int total = MROWS*CPAD + DM*CPAD;
        pad_kernel<<<(total + 255)/256, 256>>>(x, inp_w);
    }

    // 1) embed GEMM (+bias +pos), K=160 (zero-padded tail)
    {
        dim3 g(DM/128, MROWS/128);
        gemm_h<4,1><<<g, 256, SMEMB(4)>>>(ph_xpad, CPAD, ph_wpad, CPAD, p_h, DM, CPAD, 0, inp_b, pos);
    }

    // 2) layers
    for (int i = 0; i < NL; i++) {
        if (i == 0)
            ln_kernel<<<MROWS, 256>>>(norm_g, norm_b);
        else
            ln_res_kernel<<<MROWS, 256>>>(norm_g + i*DM, norm_b + i*DM);

        // in-proj -> half xz (EPI=4), ldc in half units
        dim3 g1(2*DI/128, MROWS/128);
        gemm_h<4,4><<<g1, 256, SMEMB(4)>>>(ph_hn, DM, ph_inw + (size_t)i*2*DI*DM, DM,
                                           (float*)ph_xz, 2*DI, DM, 0, nullptr, nullptr);

        conv_kernel<<<(MROWS*DI/2 + 255)/256, 256>>>(conv_w + (size_t)i*DI*4, conv_b + (size_t)i*DI);

        // xproj: N=64 (NT=2), split-K x4 into g_xsp, reduced to h_xd
        dim3 g2(1, MROWS/128, 4);
        gemm_h<2,0><<<g2, 256, SMEMB(2)>>>(ph_xc, DI, ph_xprojw + (size_t)i*64*DI, DI,
                                           p_xsp, 64, DI/4, MROWS*64, nullptr, nullptr);
        reduce4_kernel<<<(MROWS*64 + 255)/256, 256>>>();

        // dt GEMM: N=1024, K=32, softplus -> half h_dt (EPI=6)
        dim3 g3(DI/128, MROWS/128);
        gemm_h<4,6><<<g3, 256, SMEMB(4)>>>(ph_xd, 64, ph_dtw + (size_t)i*DI*DTR, DTR,
                                           (float*)ph_dt, DI, DTR, 0, dt_b + (size_t)i*DI, nullptr);

        // scan
        dim3 gs(DI/128, BB);
        scan_kernel<<<gs, 128>>>(A_log + (size_t)i*DI*NS, Dp + (size_t)i*DI);

        // out-proj: split-K x2 into half h_osp (EPI=5); folded by next ln_res
        dim3 g4(DM/128, MROWS/128, 2);
        gemm_h<4,5><<<g4, 256, SMEMB(4)>>>(ph_yg, DI, ph_outw + (size_t)i*DM*DI, DI,
                                           (float*)ph_osp, DM, DI/2, MROWS*DM, nullptr, nullptr);
    }

    // 3) fold last out-proj, final LN (last timestep) + head
    reduce_res_kernel<<<(MROWS*DM + 255)/256, 256>>>();
    ln_final_kernel<<<BB, 256>>>(lnf_g, lnf_b);
    head1_kernel<<<BB, 512>>>(op1_w, op1_b);
    head2_kernel<<<BB, 128>>>(op2_w, op2_b, outp);
}

// round 14
// speedup vs baseline: 1.1070x; 1.0204x over previous
#include <cuda_runtime.h>
#include <cuda_fp16.h>
#include <math.h>
#include <stdint.h>

#define BB 32
#define LL 100
#define CC 142
#define DM 512
#define DI 1024
#define NS 16
#define DTR 32
#define NL 6
#define OD 128
#define MROWS (BB*LL)
#define CPAD 160
#define SROWH 40   // smem row stride in halves: 80B, 16B-aligned, LDSM conflict-free
#define XSP 8      // xproj split-K slices

// fp32 state / GEMM outputs
__device__ __align__(16) float g_h   [MROWS*DM];
__device__ __align__(16) float g_xsp [XSP*MROWS*64];
// fp16 GEMM operands / activations
__device__ __align__(16) __half h_osp  [2*MROWS*DM];
__device__ __align__(16) __half h_dt   [MROWS*DI];
__device__ __align__(16) __half h_inw  [NL*2*DI*DM];
__device__ __align__(16) __half h_outw [NL*DM*DI];
__device__ __align__(16) __half h_xprojw[NL*64*DI];
__device__ __align__(16) __half h_dtw  [NL*DI*DTR];
__device__ __align__(16) __half h_xpad [MROWS*CPAD];
__device__ __align__(16) __half h_wpad [DM*CPAD];
__device__ __align__(16) __half h_hn   [MROWS*DM];
__device__ __align__(16) __half h_xz   [MROWS*2*DI];
__device__ __align__(16) __half h_xc   [MROWS*DI];
__device__ __align__(16) __half h_xd   [MROWS*64];
__device__ __align__(16) __half h_yg   [MROWS*DI];

#define Q1 (NL*2*DI*DM/4)
#define Q2 (NL*DM*DI/4)
#define Q3 (NL*64*DI/4)
#define Q4 (NL*DI*DTR/4)

// one launch converts all weight tensors (vec4)
__global__ void f2h_all_kernel(const float* __restrict__ in_w, const float* __restrict__ out_w,
                               const float* __restrict__ xproj_w, const float* __restrict__ dt_w)
{
    int i = blockIdx.x * 256 + threadIdx.x;
    const float* src; __half* dst; int k;
    if (i < Q1)                { src = in_w;    dst = h_inw;    k = i; }
    else if (i < Q1+Q2)        { src = out_w;   dst = h_outw;   k = i - Q1; }
    else if (i < Q1+Q2+Q3)     { src = xproj_w; dst = h_xprojw; k = i - Q1 - Q2; }
    else if (i < Q1+Q2+Q3+Q4)  { src = dt_w;    dst = h_dtw;    k = i - Q1 - Q2 - Q3; }
    else return;
    float4 v = ((const float4*)src)[k];
    __half2* d2 = (__half2*)dst;
    d2[k*2]   = __floats2half2_rn(v.x, v.y);
    d2[k*2+1] = __floats2half2_rn(v.z, v.w);
}

// pad + convert embed operands (K=142 -> 160, zero tail)
__global__ void pad_kernel(const float* __restrict__ x, const float* __restrict__ w)
{
    int i = blockIdx.x * 256 + threadIdx.x;
    if (i < MROWS*CPAD) {
        int m = i / CPAD, c = i % CPAD;
        h_xpad[i] = (c < CC) ? __float2half(x[m*CC + c]) : __half(0.f);
    }
    int j = i - MROWS*CPAD;
    if (j >= 0 && j < DM*CPAD) {
        int m = j / CPAD, c = j % CPAD;
        h_wpad[j] = (c < CC) ? __float2half(w[m*CC + c]) : __half(0.f);
    }
}

__device__ __forceinline__ void mma_f16(float* c, const unsigned* a, const unsigned* b)
{
    asm volatile(
        "mma.sync.aligned.m16n8k16.row.col.f32.f16.f16.f32 "
        "{%0,%1,%2,%3}, {%4,%5,%6,%7}, {%8,%9}, {%0,%1,%2,%3};"
        : "+f"(c[0]), "+f"(c[1]), "+f"(c[2]), "+f"(c[3])
        : "r"(a[0]), "r"(a[1]), "r"(a[2]), "r"(a[3]),
          "r"(b[0]), "r"(b[1]));
}
#define LDSM4(r0,r1,r2,r3,addr) \
    asm volatile("ldmatrix.sync.aligned.m8n8.x4.shared.b16 {%0,%1,%2,%3}, [%4];" \
                 : "=r"(r0),"=r"(r1),"=r"(r2),"=r"(r3) : "r"(addr))
__device__ __forceinline__ void cp16(unsigned dst, const __half* src) {
    asm volatile("cp.async.cg.shared.global [%0], [%1], 16;\n" :: "r"(dst), "l"(src));
}
__device__ __forceinline__ void cp_commit() { asm volatile("cp.async.commit_group;\n"); }
template<int N>
__device__ __forceinline__ void cp_wait() { asm volatile("cp.async.wait_group %0;\n" :: "n"(N)); }

// FP16 mma GEMM, ldmatrix operand fetch, 4-stage cp.async ring.
// C[M,N] = A[M,K](h) * W[N,K](h)^T (+epilogue). CTA 128 x 32*NT, 8 warps (2x4).
// blockIdx.z = split-K slice (k-offset z*Kk halves, C offset z*cOff).
// EPI: 0 fp32 store (+split-K off), 1 fp32 +bias+pos, 4 half store,
//      5 half store (+split-K off), 6 half softplus(+bias)
template<int NT, int EPI>
__global__ void __launch_bounds__(256) gemm_h(
    const __half* __restrict__ A, int lda,
    const __half* __restrict__ W, int ldw,
    float* __restrict__ C, int ldc,
    int Kk, int cOff,
    const float* __restrict__ bias,
    const float* __restrict__ pos)
{
    constexpr int BN = 32*NT;
    constexpr int STAGE_H = (128 + BN) * SROWH;
    constexpr int BCH = (NT >= 2) ? NT/2 : 1;
    constexpr int NPR = NT/2;

    extern __shared__ __align__(16) __half smem[];
    const unsigned smem_u = (unsigned)__cvta_generic_to_shared(smem);

    const int tid  = threadIdx.x;
    const int lane = tid & 31;
    const int wid  = tid >> 5;
    const int warp_m = wid & 1;
    const int warp_n = wid >> 1;
    const int m0 = blockIdx.y * 128;
    const int n0 = blockIdx.x * BN;
    const int zoff = blockIdx.z * Kk;

    unsigned sA[2]; const __half* gA[2];
    #pragma unroll
    for (int j = 0; j < 2; j++) {
        int u = tid + j*256, r = u >> 2, kc = (u & 3)*8;
        sA[j] = smem_u + (r*SROWH + kc)*2;
        gA[j] = A + (size_t)(m0 + r)*lda + zoff + kc;
    }
    unsigned sB[BCH]; const __half* gB[BCH];
    #pragma unroll
    for (int j = 0; j < BCH; j++) {
        int u = tid + j*256, r = u >> 2, kc = (u & 3)*8;
        sB[j] = smem_u + ((128 + r)*SROWH + kc)*2;
        gB[j] = W + (size_t)(n0 + r)*ldw + zoff + kc;
    }

    const int sub = lane >> 3, r8 = lane & 7;
    unsigned aoff[2][4];
    #pragma unroll
    for (int ks = 0; ks < 2; ks++)
        #pragma unroll
        for (int mt = 0; mt < 4; mt++) {
            int row = warp_m*64 + mt*16 + (sub & 1)*8 + r8;
            int kb  = ks*16 + (sub >> 1)*8;
            aoff[ks][mt] = (unsigned)((row*SROWH + kb)*2);
        }
    unsigned boff[2][NPR];
    #pragma unroll
    for (int ks = 0; ks < 2; ks++)
        #pragma unroll
        for (int pr = 0; pr < NPR; pr++) {
            int nt2 = sub >> 1;
            int kb  = ks*16 + (sub & 1)*8;
            int row = 128 + warp_n*(NT*8) + (pr*2 + nt2)*8 + r8;
            boff[ks][pr] = (unsigned)((row*SROWH + kb)*2);
        }

    const int iters = Kk >> 5;

    #pragma unroll
    for (int s = 0; s < 3; s++) {
        if (s < iters) {
            int ko = s*32;
            unsigned so = (unsigned)(s*STAGE_H*2);
            #pragma unroll
            for (int j = 0; j < 2; j++)   cp16(sA[j] + so, gA[j] + ko);
            #pragma unroll
            for (int j = 0; j < BCH; j++) cp16(sB[j] + so, gB[j] + ko);
        }
        cp_commit();
    }

    float acc[4][NT][4];
    #pragma unroll
    for (int i = 0; i < 4; i++)
        #pragma unroll
        for (int j = 0; j < NT; j++)
            #pragma unroll
            for (int r = 0; r < 4; r++) acc[i][j][r] = 0.f;

    int stg = 0;
    for (int it = 0; it < iters; it++) {
        cp_wait<2>();
        __syncthreads();

        {
            int nit = it + 3;
            if (nit < iters) {
                int ko = nit*32;
                int ns = (stg + 3) & 3;
                unsigned so = (unsigned)(ns*STAGE_H*2);
                #pragma unroll
                for (int j = 0; j < 2; j++)   cp16(sA[j] + so, gA[j] + ko);
                #pragma unroll
                for (int j = 0; j < BCH; j++) cp16(sB[j] + so, gB[j] + ko);
            }
            cp_commit();
        }

        const unsigned sbase = smem_u + (unsigned)(stg*STAGE_H*2);

        #pragma unroll
        for (int ks = 0; ks < 2; ks++) {
            unsigned afr[4][4], bfr[NT][2];
            #pragma unroll
            for (int mt = 0; mt < 4; mt++)
                LDSM4(afr[mt][0], afr[mt][1], afr[mt][2], afr[mt][3], sbase + aoff[ks][mt]);
            #pragma unroll
            for (int pr = 0; pr < NPR; pr++)
                LDSM4(bfr[pr*2][0], bfr[pr*2][1], bfr[pr*2+1][0], bfr[pr*2+1][1],
                      sbase + boff[ks][pr]);
            #pragma unroll
            for (int mt = 0; mt < 4; mt++)
                #pragma unroll
                for (int nt = 0; nt < NT; nt++)
                    mma_f16(acc[mt][nt], afr[mt], bfr[nt]);
        }

        stg = (stg + 1) & 3;
    }

    float* Cz = C + (size_t)blockIdx.z * cOff;
    __half* Ch = (__half*)C;
    __half* Chz = (__half*)C + (size_t)blockIdx.z * cOff;
    #pragma unroll
    for (int mt = 0; mt < 4; mt++) {
        #pragma unroll
        for (int rr = 0; rr < 2; rr++) {
            int r = m0 + warp_m*64 + mt*16 + (lane >> 2) + rr*8;
            #pragma unroll
            for (int nt = 0; nt < NT; nt++) {
                int c = n0 + warp_n*(NT*8) + nt*8 + (lane & 3)*2;
                float v0 = acc[mt][nt][rr*2 + 0];
                float v1 = acc[mt][nt][rr*2 + 1];
                size_t o = (size_t)r*ldc + c;
                if (EPI == 0) {
                    Cz[o]   = v0;
                    Cz[o+1] = v1;
                } else if (EPI == 1) {
                    const float* pr = pos + (size_t)(r % LL)*DM;
                    Cz[o]   = v0 + bias[c]   + pr[c];
                    Cz[o+1] = v1 + bias[c+1] + pr[c+1];
                } else if (EPI == 4) {
                    *(__half2*)(Ch + o) = __floats2half2_rn(v0, v1);
                } else if (EPI == 5) {
                    *(__half2*)(Chz + o) = __floats2half2_rn(v0, v1);
                } else if (EPI == 6) {
                    float u0 = v0 + bias[c];
                    float u1 = v1 + bias[c+1];
                    // branch-free softplus: max(u,0) + log(1+exp(-|u|))
                    u0 = fmaxf(u0, 0.f) + __logf(1.f + __expf(-fabsf(u0)));
                    u1 = fmaxf(u1, 0.f) + __logf(1.f + __expf(-fabsf(u1)));
                    *(__half2*)(Ch + o) = __floats2half2_rn(u0, u1);
                }
            }
        }
    }
}

// reduce XSP xproj split-K slices -> h_xd (half)
__global__ void reduce8_kernel()
{
    int i = blockIdx.x * 256 + threadIdx.x;
    if (i < MROWS*64) {
        const int S = MROWS*64;
        float s = 0.f;
        #pragma unroll
        for (int k = 0; k < XSP; k++) s += g_xsp[i + k*S];
        h_xd[i] = __float2half(s);
    }
}

// LN: hn(half) = LN(h). 2 rows/block, 128 thr/row, float4.
__global__ void ln_kernel(const float* __restrict__ g, const float* __restrict__ b)
{
    int tid = threadIdx.x;
    int sub = tid >> 7, lt = tid & 127;
    int row = blockIdx.x*2 + sub;
    size_t ob = (size_t)row * DM;
    float4 v = *(const float4*)&g_h[ob + lt*4];
    float s = (v.x + v.y) + (v.z + v.w);
    float sq = (v.x*v.x + v.y*v.y) + (v.z*v.z + v.w*v.w);
    #pragma unroll
    for (int o = 16; o; o >>= 1) {
        s  += __shfl_xor_sync(0xffffffffu, s,  o);
        sq += __shfl_xor_sync(0xffffffffu, sq, o);
    }
    __shared__ float ss[8], ssq[8];
    int wid = tid >> 5;
    if ((tid & 31) == 0) { ss[wid] = s; ssq[wid] = sq; }
    __syncthreads();
    int base = sub*4;
    float ts  = (ss[base] + ss[base+1]) + (ss[base+2] + ss[base+3]);
    float tsq = (ssq[base] + ssq[base+1]) + (ssq[base+2] + ssq[base+3]);
    float mean = ts * (1.f/DM);
    float var  = tsq * (1.f/DM) - mean*mean;
    float rs = rsqrtf(var + 1e-5f);
    float4 gg = *(const float4*)&g[lt*4];
    float4 bb = *(const float4*)&b[lt*4];
    __half2 o0 = __floats2half2_rn((v.x - mean)*rs*gg.x + bb.x, (v.y - mean)*rs*gg.y + bb.y);
    __half2 o1 = __floats2half2_rn((v.z - mean)*rs*gg.z + bb.z, (v.w - mean)*rs*gg.w + bb.w);
    uint2 pk; pk.x = *(unsigned*)&o0; pk.y = *(unsigned*)&o1;
    *(uint2*)&h_hn[ob + lt*4] = pk;
}

// fused: h += osp0+osp1 (half slices), then hn(half) = LN(h). 2 rows/block, float4.
__global__ void ln_res_kernel(const float* __restrict__ g, const float* __restrict__ b)
{
    int tid = threadIdx.x;
    int sub = tid >> 7, lt = tid & 127;
    int row = blockIdx.x*2 + sub;
    size_t ob = (size_t)row * DM;
    const int S = MROWS*DM;
    float4 v = *(const float4*)&g_h[ob + lt*4];
    uint2 r0 = *(const uint2*)&h_osp[ob + lt*4];
    uint2 r1 = *(const uint2*)&h_osp[ob + lt*4 + S];
    float2 a0 = __half22float2(*(__half2*)&r0.x);
    float2 a1 = __half22float2(*(__half2*)&r0.y);
    float2 b0 = __half22float2(*(__half2*)&r1.x);
    float2 b1 = __half22float2(*(__half2*)&r1.y);
    v.x += a0.x + b0.x; v.y += a0.y + b0.y;
    v.z += a1.x + b1.x; v.w += a1.y + b1.y;
    *(float4*)&g_h[ob + lt*4] = v;
    float s = (v.x + v.y) + (v.z + v.w);
    float sq = (v.x*v.x + v.y*v.y) + (v.z*v.z + v.w*v.w);
    #pragma unroll
    for (int o = 16; o; o >>= 1) {
        s  += __shfl_xor_sync(0xffffffffu, s,  o);
        sq += __shfl_xor_sync(0xffffffffu, sq, o);
    }
    __shared__ float ss[8], ssq[8];
    int wid = tid >> 5;
    if ((tid & 31) == 0) { ss[wid] = s; ssq[wid] = sq; }
    __syncthreads();
    int base = sub*4;
    float ts  = (ss[base] + ss[base+1]) + (ss[base+2] + ss[base+3]);
    float tsq = (ssq[base] + ssq[base+1]) + (ssq[base+2] + ssq[base+3]);
    float mean = ts * (1.f/DM);
    float var  = tsq * (1.f/DM) - mean*mean;
    float rs = rsqrtf(var + 1e-5f);
    float4 gg = *(const float4*)&g[lt*4];
    float4 bb = *(const float4*)&b[lt*4];
    __half2 o0 = __floats2half2_rn((v.x - mean)*rs*gg.x + bb.x, (v.y - mean)*rs*gg.y + bb.y);
    __half2 o1 = __floats2half2_rn((v.z - mean)*rs*gg.z + bb.z, (v.w - mean)*rs*gg.w + bb.w);
    uint2 pk; pk.x = *(unsigned*)&o0; pk.y = *(unsigned*)&o1;
    *(uint2*)&h_hn[ob + lt*4] = pk;
}

// depthwise causal conv (K=4) + bias + silu ; 4 channels per thread
__global__ void conv_kernel(const float* __restrict__ cw, const float* __restrict__ cb)
{
    int idx = blockIdx.x * 256 + threadIdx.x;
    if (idx >= MROWS*DI/4) return;
    int dq = idx & (DI/4 - 1);
    int m  = idx >> 8;
    int d  = dq*4;
    int t  = m % LL;
    float4 w0 = *(const float4*)&cw[d*4];
    float4 w1 = *(const float4*)&cw[d*4 + 4];
    float4 w2 = *(const float4*)&cw[d*4 + 8];
    float4 w3 = *(const float4*)&cw[d*4 + 12];
    float4 cbv = *(const float4*)&cb[d];
    size_t rb = (size_t)m * (2*DI) + d;
    uint2 raw = *(const uint2*)&h_xz[rb];
    float2 x01 = __half22float2(*(__half2*)&raw.x);
    float2 x23 = __half22float2(*(__half2*)&raw.y);
    float a0 = cbv.x + x01.x * w0.w;
    float a1 = cbv.y + x01.y * w1.w;
    float a2 = cbv.z + x23.x * w2.w;
    float a3 = cbv.w + x23.y * w3.w;
    if (t >= 1) {
        uint2 r = *(const uint2*)&h_xz[rb - 1*2*DI];
        float2 y01 = __half22float2(*(__half2*)&r.x);
        float2 y23 = __half22float2(*(__half2*)&r.y);
        a0 += y01.x * w0.z; a1 += y01.y * w1.z; a2 += y23.x * w2.z; a3 += y23.y * w3.z;
    }
    if (t >= 2) {
        uint2 r = *(const uint2*)&h_xz[rb - 2*2*DI];
        float2 y01 = __half22float2(*(__half2*)&r.x);
        float2 y23 = __half22float2(*(__half2*)&r.y);
        a0 += y01.x * w0.y; a1 += y01.y * w1.y; a2 += y23.x * w2.y; a3 += y23.y * w3.y;
    }
    if (t >= 3) {
        uint2 r = *(const uint2*)&h_xz[rb - 3*2*DI];
        float2 y01 = __half22float2(*(__half2*)&r.x);
        float2 y23 = __half22float2(*(__half2*)&r.y);
        a0 += y01.x * w0.x; a1 += y01.y * w1.x; a2 += y23.x * w2.x; a3 += y23.y * w3.x;
    }
    float s0 = a0 / (1.f + __expf(-a0));
    float s1 = a1 / (1.f + __expf(-a1));
    float s2 = a2 / (1.f + __expf(-a2));
    float s3 = a3 / (1.f + __expf(-a3));
    __half2 p0 = __floats2half2_rn(s0, s1);
    __half2 p1 = __floats2half2_rn(s2, s3);
    uint2 pk; pk.x = *(unsigned*)&p0; pk.y = *(unsigned*)&p1;
    *(uint2*)&h_xc[(size_t)m*DI + d] = pk;
}

// scan: B/C staged in smem, no barriers in t-loop, prefetch next inputs.
// exp-power chain via log-depth tree; acc split into 4 partials.
__global__ void __launch_bounds__(128) scan_kernel(const float* __restrict__ A_log,
                                                   const float* __restrict__ Dp)
{
    int b = blockIdx.y;
    int tid = threadIdx.x;
    int d = blockIdx.x * 128 + tid;
    __shared__ float sB[LL*NS], sC[LL*NS];

    size_t bbase = (size_t)b * LL;
    for (int u = tid; u < LL*32; u += 128) {
        int t = u >> 5, j = u & 31;
        float v = __half2float(h_xd[(bbase + t)*64 + 32 + j]);
        if (j < NS) sB[t*NS + j] = v;
        else        sC[t*NS + (j - NS)] = v;
    }

    float hs[NS], Af[NS];
    #pragma unroll
    for (int n = 0; n < NS; n++) {
        hs[n] = 0.f;
        Af[n] = -__expf(A_log[(size_t)d*NS + n]);
    }
    float base = Af[0];
    bool chain = true;
    #pragma unroll
    for (int n = 0; n < NS; n++) {
        float want = (float)(n+1) * base;
        chain = chain && (fabsf(Af[n] - want) <= 1e-4f*fabsf(want) + 1e-6f);
    }
    float Dpd = Dp[d];
    __syncthreads();

    float xcv = __half2float(h_xc[bbase*DI + d]);
    float dtv = __half2float(h_dt[bbase*DI + d]);
    float zv  = __half2float(h_xz[bbase*2*DI + DI + d]);

    for (int t = 0; t < LL; t++) {
        float nxc = 0.f, ndt = 0.f, nz = 0.f;
        if (t + 1 < LL) {
            size_t mn = bbase + t + 1;
            nxc = __half2float(h_xc[mn*DI + d]);
            ndt = __half2float(h_dt[mn*DI + d]);
            nz  = __half2float(h_xz[mn*2*DI + DI + d]);
        }
        const float* Bp = &sB[t*NS];
        const float* Cp = &sC[t*NS];
        float dtx = dtv * xcv;
        float a0 = 0.f, a1 = 0.f, a2 = 0.f, a3 = 0.f;
        if (chain) {
            float e1 = __expf(dtv * base);
            float e2 = e1*e1, e4 = e2*e2, e8 = e4*e4;
            float p3 = e2*e1, p5 = e4*e1, p6 = e4*e2, p7 = e4*p3;
            float pw[NS] = { e1, e2, p3, e4, p5, p6, p7, e8,
                             e8*e1, e8*e2, e8*p3, e8*e4, e8*p5, e8*p6, e8*p7, e8*e8 };
            #pragma unroll
            for (int n = 0; n < NS; n++) {
                hs[n] = fmaf(pw[n], hs[n], dtx * Bp[n]);
                float v = hs[n] * Cp[n];
                if ((n & 3) == 0) a0 += v;
                else if ((n & 3) == 1) a1 += v;
                else if ((n & 3) == 2) a2 += v;
                else a3 += v;
            }
        } else {
            #pragma unroll
            for (int n = 0; n < NS; n++) {
                float dA = __expf(dtv * Af[n]);
                hs[n] = fmaf(dA, hs[n], dtx * Bp[n]);
                float v = hs[n] * Cp[n];
                if ((n & 3) == 0) a0 += v;
                else if ((n & 3) == 1) a1 += v;
                else if ((n & 3) == 2) a2 += v;
                else a3 += v;
            }
        }
        float acc = (a0 + a1) + (a2 + a3);
        float y = acc + Dpd * xcv;
        float sig = 1.f / (1.f + __expf(-zv));
        h_yg[(bbase + t)*DI + d] = __float2half(y * (zv * sig));
        xcv = nxc; dtv = ndt; zv = nz;
    }
}

// fused tail: fold last-layer osp (last timestep only) + final LN + head1 + head2.
// one block per batch, 512 threads.
__global__ void __launch_bounds__(512) head_kernel(
    const float* __restrict__ lnf_g, const float* __restrict__ lnf_b,
    const float* __restrict__ op1_w, const float* __restrict__ op1_b,
    const float* __restrict__ op2_w, const float* __restrict__ op2_b,
    float* __restrict__ out)
{
    int b = blockIdx.x;
    int j = threadIdx.x;   // 512
    __shared__ float xr[DM], hid[DM], ss[16], ssq[16];
    size_t ob = (size_t)(b*LL + LL-1) * DM;
    const int S = MROWS*DM;
    float v = g_h[ob + j] + __half2float(h_osp[ob + j]) + __half2float(h_osp[ob + j + S]);
    float s = v, sq = v*v;
    #pragma unroll
    for (int o = 16; o; o >>= 1) {
        s  += __shfl_xor_sync(0xffffffffu, s,  o);
        sq += __shfl_xor_sync(0xffffffffu, sq, o);
    }
    if ((j & 31) == 0) { ss[j>>5] = s; ssq[j>>5] = sq; }
    __syncthreads();
    float ts = 0.f, tsq = 0.f;
    #pragma unroll
    for (int i = 0; i < 16; i++) { ts += ss[i]; tsq += ssq[i]; }
    float mean = ts * (1.f/DM);
    float var  = tsq * (1.f/DM) - mean*mean;
    float rs = rsqrtf(var + 1e-5f);
    xr[j] = (v - mean)*rs*lnf_g[j] + lnf_b[j];
    __syncthreads();
    // head1: gelu(xr @ op1^T + b1)
    {
        const float4* wr = (const float4*)(op1_w + (size_t)j*DM);
        float s1 = op1_b[j];
        #pragma unroll 4
        for (int k = 0; k < DM/4; k++) {
            float4 wv = wr[k];
            const float* xv = &xr[k*4];
            s1 = fmaf(wv.x, xv[0], s1);
            s1 = fmaf(wv.y, xv[1], s1);
            s1 = fmaf(wv.z, xv[2], s1);
            s1 = fmaf(wv.w, xv[3], s1);
        }
        hid[j] = 0.5f * s1 * (1.f + erff(s1 * 0.70710678118654752f));
    }
    __syncthreads();
    // head2: hid @ op2^T + b2
    if (j < OD) {
        const float4* wr = (const float4*)(op2_w + (size_t)j*DM);
        float s2 = op2_b[j];
        #pragma unroll 4
        for (int k = 0; k < DM/4; k++) {
            float4 wv = wr[k];
            const float* xv = &hid[k*4];
            s2 = fmaf(wv.x, xv[0], s2);
            s2 = fmaf(wv.y, xv[1], s2);
            s2 = fmaf(wv.z, xv[2], s2);
            s2 = fmaf(wv.w, xv[3], s2);
        }
        out[(size_t)b*OD + j] = s2;
    }
}

#define SMEMB(NT) (4*(128 + 32*(NT))*SROWH*2)

extern "C" void kernel_launch(void* const* d_in, const int* in_sizes, int n_in,
                              void* d_out, int out_size)
{
    const float* x      = (const float*)d_in[0];
    const float* inp_w  = (const float*)d_in[1];
    const float* inp_b  = (const float*)d_in[2];
    const float* pos    = (const float*)d_in[3];
    const float* norm_g = (const float*)d_in[4];
    const float* norm_b = (const float*)d_in[5];
    const float* in_w   = (const float*)d_in[6];
    const float* conv_w = (const float*)d_in[7];
    const float* conv_b = (const float*)d_in[8];
    const float* xproj_w= (const float*)d_in[9];
    const float* dt_w   = (const float*)d_in[10];
    const float* dt_b   = (const float*)d_in[11];
    const float* A_log  = (const float*)d_in[12];
    const float* Dp     = (const float*)d_in[13];
    const float* out_w  = (const float*)d_in[14];
    const float* lnf_g  = (const float*)d_in[15];
    const float* lnf_b  = (const float*)d_in[16];
    const float* op1_w  = (const float*)d_in[17];
    const float* op1_b  = (const float*)d_in[18];
    const float* op2_w  = (const float*)d_in[19];
    const float* op2_b  = (const float*)d_in[20];
    float* outp = (float*)d_out;

    __half *ph_inw, *ph_outw, *ph_xprojw, *ph_dtw, *ph_xpad, *ph_wpad, *ph_hn, *ph_xz, *ph_xc, *ph_xd, *ph_yg, *ph_osp, *ph_dt;
    cudaGetSymbolAddress((void**)&ph_inw,   h_inw);
    cudaGetSymbolAddress((void**)&ph_outw,  h_outw);
    cudaGetSymbolAddress((void**)&ph_xprojw,h_xprojw);
    cudaGetSymbolAddress((void**)&ph_dtw,   h_dtw);
    cudaGetSymbolAddress((void**)&ph_xpad,  h_xpad);
    cudaGetSymbolAddress((void**)&ph_wpad,  h_wpad);
    cudaGetSymbolAddress((void**)&ph_hn,    h_hn);
    cudaGetSymbolAddress((void**)&ph_xz,    h_xz);
    cudaGetSymbolAddress((void**)&ph_xc,    h_xc);
    cudaGetSymbolAddress((void**)&ph_xd,    h_xd);
    cudaGetSymbolAddress((void**)&ph_yg,    h_yg);
    cudaGetSymbolAddress((void**)&ph_osp,   h_osp);
    cudaGetSymbolAddress((void**)&ph_dt,    h_dt);
    float *p_h, *p_xsp;
    cudaGetSymbolAddress((void**)&p_h,   g_h);
    cudaGetSymbolAddress((void**)&p_xsp, g_xsp);

    cudaFuncSetAttribute(gemm_h<4,1>, cudaFuncAttributeMaxDynamicSharedMemorySize, SMEMB(4));
    cudaFuncSetAttribute(gemm_h<4,4>, cudaFuncAttributeMaxDynamicSharedMemorySize, SMEMB(4));
    cudaFuncSetAttribute(gemm_h<4,5>, cudaFuncAttributeMaxDynamicSharedMemorySize, SMEMB(4));
    cudaFuncSetAttribute(gemm_h<4,6>, cudaFuncAttributeMaxDynamicSharedMemorySize, SMEMB(4));
    cudaFuncSetAttribute(gemm_h<2,0>, cudaFuncAttributeMaxDynamicSharedMemorySize, SMEMB(2));

    // 0) weight conversion (one launch) + embed pad/convert
    {
        int qtot = Q1 + Q2 + Q3 + Q4;
        f2h_all_kernel<<<(qtot + 255)/256, 256>>>(in_w, out_w, xproj_w, dt_w);
        int total = MROWS*CPAD + DM*CPAD;
        pad_kernel<<<(total + 255)/256, 256>>>(x, inp_w);
    }

    // 1) embed GEMM (+bias +pos), K=160 (zero-padded tail)
    {
        dim3 g(DM/128, MROWS/128);
        gemm_h<4,1><<<g, 256, SMEMB(4)>>>(ph_xpad, CPAD, ph_wpad, CPAD, p_h, DM, CPAD, 0, inp_b, pos);
    }

    // 2) layers
    for (int i = 0; i < NL; i++) {
        if (i == 0)
            ln_kernel<<<MROWS/2, 256>>>(norm_g, norm_b);
        else
            ln_res_kernel<<<MROWS/2, 256>>>(norm_g + i*DM, norm_b + i*DM);

        // in-proj -> half xz (EPI=4), ldc in half units
        dim3 g1(2*DI/128, MROWS/128);
        gemm_h<4,4><<<g1, 256, SMEMB(4)>>>(ph_hn, DM, ph_inw + (size_t)i*2*DI*DM, DM,
                                           (float*)ph_xz, 2*DI, DM, 0, nullptr, nullptr);

        conv_kernel<<<(MROWS*DI/4 + 255)/256, 256>>>(conv_w + (size_t)i*DI*4, conv_b + (size_t)i*DI);

        // xproj: N=64 (NT=2), split-K x8 into g_xsp, reduced to h_xd
        dim3 g2(1, MROWS/128, XSP);
        gemm_h<2,0><<<g2, 256, SMEMB(2)>>>(ph_xc, DI, ph_xprojw + (size_t)i*64*DI, DI,
                                           p_xsp, 64, DI/XSP, MROWS*64, nullptr, nullptr);
        reduce8_kernel<<<(MROWS*64 + 255)/256, 256>>>();

        // dt GEMM: N=1024, K=32, softplus -> half h_dt (EPI=6)
        dim3 g3(DI/128, MROWS/128);
        gemm_h<4,6><<<g3, 256, SMEMB(4)>>>(ph_xd, 64, ph_dtw + (size_t)i*DI*DTR, DTR,
                                           (float*)ph_dt, DI, DTR, 0, dt_b + (size_t)i*DI, nullptr);

        // scan
        dim3 gs(DI/128, BB);
        scan_kernel<<<gs, 128>>>(A_log + (size_t)i*DI*NS, Dp + (size_t)i*DI);

        // out-proj: split-K x2 into half h_osp (EPI=5); folded by next ln_res / head
        dim3 g4(DM/128, MROWS/128, 2);
        gemm_h<4,5><<<g4, 256, SMEMB(4)>>>(ph_yg, DI, ph_outw + (size_t)i*DM*DI, DI,
                                           (float*)ph_osp, DM, DI/2, MROWS*DM, nullptr, nullptr);
    }

    // 3) fused tail: last-row residual fold + final LN + head
    head_kernel<<<BB, 512>>>(lnf_g, lnf_b, op1_w, op1_b, op2_w, op2_b, outp);
}